// round 1
// baseline (speedup 1.0000x reference)
#include <cuda_runtime.h>
#include <math.h>

// ---------------- problem constants ----------------
#define NB 16
#define NC 128
#define HH 64
#define WW 64
#define HW 4096           // 64*64
#define CHW (NC*HW)       // 524288
#define AUXC 277

// ---------------- scratch (device globals; no allocs) ----------------
__device__ float g_aux  [NB*AUXC*HW];     // concat(edge,seg,pred_edge,pred_seg)
__device__ float g_a    [NB*CHW];         // embed(aux)
__device__ float g_gamma[NB*CHW];
__device__ float g_betaS[NB*CHW];         // shared half of beta (+bias)
__device__ float g_t0   [NB*CHW];         // conv1x1 pre-ADN temp
__device__ float g_q    [NB*CHW];
__device__ float g_k    [NB*CHW];
__device__ float g_v    [NB*CHW];
__device__ float g_mid  [NB*CHW];
__device__ float g_o    [NB*CHW];
__device__ float g_gf   [NB*CHW];         // tanh(conv3x3 sc)
__device__ float g_tmp  [NB*CHW];         // gelu(conv3x3 bi1)
__device__ float g_qp1  [NB*1024*256];
__device__ float g_kp1  [NB*1024*256];
__device__ float g_vp1  [NB*1024*256];
__device__ float g_qp2  [NB*256*1024];
__device__ float g_kp2  [NB*256*1024];
__device__ float g_vp2  [NB*256*1024];
__device__ float g_s1   [NB*1024*1024];
__device__ float g_s2   [NB*256*256];
__device__ float g_y1   [NB*1024*256];
__device__ float g_y2   [NB*256*1024];
__device__ float g_stats[NB*2];           // mu, rstd per batch
__device__ float g_part [NB*64*2];        // LN partial sums

// ---------------- epilogue modes ----------------
#define EP_BIAS  0
#define EP_ADN   1
#define EP_NONE  2
#define EP_TANH  3
#define EP_GELU  4
#define EP_FINAL 5

// ================= concat aux =================
__global__ void __launch_bounds__(256)
concat_aux_kernel(const float* __restrict__ edge, const float* __restrict__ seg,
                  const float* __restrict__ pe,   const float* __restrict__ ps) {
    long i = (long)blockIdx.x * blockDim.x + threadIdx.x;
    long total = (long)NB * AUXC * HW;
    if (i >= total) return;
    int p = (int)(i % HW);
    long t = i / HW;
    int c = (int)(t % AUXC);
    int b = (int)(t / AUXC);
    float v;
    if (c < 128)       v = edge[((long)b*128 + c)      * HW + p];
    else if (c < 256)  v = seg [((long)b*128 + (c-128))* HW + p];
    else if (c == 256) v = pe  [(long)b * HW + p];
    else               v = ps  [((long)b*20 + (c-257)) * HW + p];
    g_aux[i] = v;
}

// ================= GEMM NN: C[m,n] = sum_k A[m,k]*B[k,n] (per batch B,C; A optionally batched) =================
__global__ void __launch_bounds__(256)
gemm_nn_kernel(const float* __restrict__ A, int lda, long sA_,
               const float* __restrict__ Bm, long sB_,
               float* __restrict__ Cm, long sC_,
               int N, int K, int mode,
               const float* __restrict__ bias,
               const float* __restrict__ t0,
               const float* __restrict__ gamma,
               const float* __restrict__ betaS,
               const float* __restrict__ stats)
{
    int bb = blockIdx.z;
    int n0 = blockIdx.x * 64;
    int m0 = blockIdx.y * 64;
    const float* Ap = A + (long)bb * sA_;
    const float* Bp = Bm + (long)bb * sB_;
    float* Cp = Cm + (long)bb * sC_;

    __shared__ float sA[16][68];
    __shared__ float sB[16][68];

    int tid = threadIdx.x;
    int tx = tid & 15, ty = tid >> 4;
    int arow = tid >> 2;            // 0..63 (m)
    int acol = (tid & 3) * 4;       // 0..12 (k)
    int brow = tid >> 4;            // 0..15 (k)
    int bcol = (tid & 15) * 4;      // 0..60 (n)

    float acc[4][4] = {};

    for (int kt = 0; kt < K; kt += 16) {
#pragma unroll
        for (int j = 0; j < 4; j++) {
            int k = kt + acol + j;
            sA[acol + j][arow] = (k < K) ? Ap[(long)(m0 + arow) * lda + k] : 0.f;
        }
        {
            int k = kt + brow;
            if (k < K) {
#pragma unroll
                for (int j = 0; j < 4; j++)
                    sB[brow][bcol + j] = Bp[(long)k * N + n0 + bcol + j];
            } else {
#pragma unroll
                for (int j = 0; j < 4; j++) sB[brow][bcol + j] = 0.f;
            }
        }
        __syncthreads();
#pragma unroll
        for (int kk = 0; kk < 16; kk++) {
            float ra[4], rb[4];
#pragma unroll
            for (int i = 0; i < 4; i++) ra[i] = sA[kk][ty * 4 + i];
#pragma unroll
            for (int j = 0; j < 4; j++) rb[j] = sB[kk][tx * 4 + j];
#pragma unroll
            for (int i = 0; i < 4; i++)
#pragma unroll
                for (int j = 0; j < 4; j++)
                    acc[i][j] = fmaf(ra[i], rb[j], acc[i][j]);
        }
        __syncthreads();
    }

    float mu = 0.f, rs = 0.f;
    if (mode == EP_ADN) { mu = stats[2 * bb]; rs = stats[2 * bb + 1]; }
#pragma unroll
    for (int i = 0; i < 4; i++) {
        int m = m0 + ty * 4 + i;
#pragma unroll
        for (int j = 0; j < 4; j++) {
            int n = n0 + tx * 4 + j;
            long idx = (long)m * N + n;
            float v = acc[i][j];
            if (mode == EP_BIAS) {
                v += bias[m];
            } else if (mode == EP_ADN) {
                long g = (long)bb * sC_ + idx;
                v = (t0[g] - mu) * rs * gamma[g] + v + betaS[g];
            }
            Cp[idx] = v;
        }
    }
}

// ================= GEMM NT: C[m,n] = scale * sum_k A[m,k]*B[n,k] (batched A,B,C) =================
__global__ void __launch_bounds__(256)
gemm_nt_kernel(const float* __restrict__ A, long sA_,
               const float* __restrict__ Bm, long sB_,
               float* __restrict__ Cm, long sC_,
               int N, int K, float scale)
{
    int bb = blockIdx.z;
    int n0 = blockIdx.x * 64;
    int m0 = blockIdx.y * 64;
    const float* Ap = A + (long)bb * sA_;
    const float* Bp = Bm + (long)bb * sB_;
    float* Cp = Cm + (long)bb * sC_;

    __shared__ float sA[16][68];
    __shared__ float sB[16][68];

    int tid = threadIdx.x;
    int tx = tid & 15, ty = tid >> 4;
    int arow = tid >> 2;
    int acol = (tid & 3) * 4;

    float acc[4][4] = {};

    for (int kt = 0; kt < K; kt += 16) {
#pragma unroll
        for (int j = 0; j < 4; j++) {
            int k = kt + acol + j;
            sA[acol + j][arow] = (k < K) ? Ap[(long)(m0 + arow) * K + k] : 0.f;
            sB[acol + j][arow] = (k < K) ? Bp[(long)(n0 + arow) * K + k] : 0.f;
        }
        __syncthreads();
#pragma unroll
        for (int kk = 0; kk < 16; kk++) {
            float ra[4], rb[4];
#pragma unroll
            for (int i = 0; i < 4; i++) ra[i] = sA[kk][ty * 4 + i];
#pragma unroll
            for (int j = 0; j < 4; j++) rb[j] = sB[kk][tx * 4 + j];
#pragma unroll
            for (int i = 0; i < 4; i++)
#pragma unroll
                for (int j = 0; j < 4; j++)
                    acc[i][j] = fmaf(ra[i], rb[j], acc[i][j]);
        }
        __syncthreads();
    }
#pragma unroll
    for (int i = 0; i < 4; i++) {
        int m = m0 + ty * 4 + i;
#pragma unroll
        for (int j = 0; j < 4; j++) {
            int n = n0 + tx * 4 + j;
            Cp[(long)m * N + n] = acc[i][j] * scale;
        }
    }
}

// ================= conv3x3 implicit GEMM: M=128, N=4096, K=1152 =================
__global__ void __launch_bounds__(256)
conv3x3_kernel(const float* __restrict__ Wt,  // [128, 1152] row-major
               const float* __restrict__ X,   // [B,128,64,64]
               float* __restrict__ Cm,
               const float* __restrict__ bias,
               int dil, int mode,
               const float* __restrict__ mid,
               const float* __restrict__ gf)
{
    const int K = 1152, N = HW;
    int bb = blockIdx.z;
    int n0 = blockIdx.x * 64;
    int m0 = blockIdx.y * 64;
    const float* Xp = X + (long)bb * CHW;
    float* Cp = Cm + (long)bb * CHW;

    __shared__ float sA[16][68];
    __shared__ float sB[16][68];

    int tid = threadIdx.x;
    int tx = tid & 15, ty = tid >> 4;
    int arow = tid >> 2;
    int acol = (tid & 3) * 4;
    int brow = tid >> 4;
    int bcol = (tid & 15) * 4;

    float acc[4][4] = {};

    for (int kt = 0; kt < K; kt += 16) {
#pragma unroll
        for (int j = 0; j < 4; j++) {
            int k = kt + acol + j;
            sA[acol + j][arow] = Wt[(long)(m0 + arow) * K + k];
        }
        {
            int k = kt + brow;
            int c  = k / 9;
            int t  = k - c * 9;
            int dy = (t / 3 - 1) * dil;
            int dx = (t % 3 - 1) * dil;
            const float* base = Xp + (long)c * HW;
#pragma unroll
            for (int j = 0; j < 4; j++) {
                int p = n0 + bcol + j;
                int h = (p >> 6) + dy;
                int w = (p & 63) + dx;
                float v = 0.f;
                if ((unsigned)h < 64u && (unsigned)w < 64u)
                    v = base[h * 64 + w];
                sB[brow][bcol + j] = v;
            }
        }
        __syncthreads();
#pragma unroll
        for (int kk = 0; kk < 16; kk++) {
            float ra[4], rb[4];
#pragma unroll
            for (int i = 0; i < 4; i++) ra[i] = sA[kk][ty * 4 + i];
#pragma unroll
            for (int j = 0; j < 4; j++) rb[j] = sB[kk][tx * 4 + j];
#pragma unroll
            for (int i = 0; i < 4; i++)
#pragma unroll
                for (int j = 0; j < 4; j++)
                    acc[i][j] = fmaf(ra[i], rb[j], acc[i][j]);
        }
        __syncthreads();
    }

#pragma unroll
    for (int i = 0; i < 4; i++) {
        int m = m0 + ty * 4 + i;
        float bv = bias[m];
#pragma unroll
        for (int j = 0; j < 4; j++) {
            int n = n0 + tx * 4 + j;
            long idx = (long)m * N + n;
            float v = acc[i][j] + bv;
            if (mode == EP_TANH) {
                v = tanhf(v);
            } else if (mode == EP_GELU) {
                v = 0.5f * v * (1.f + erff(v * 0.70710678118654752f));
            } else if (mode == EP_FINAL) {
                long g = (long)bb * CHW + idx;
                v = mid[g] * gf[g] + v;
            }
            Cp[idx] = v;
        }
    }
}

// ================= LayerNorm stats (2-stage, deterministic) =================
__global__ void __launch_bounds__(256)
ln_part_kernel(const float* __restrict__ src) {
    int b = blockIdx.y, ch = blockIdx.x;          // 64 chunks
    const int CH = CHW / 64;                      // 8192
    const float* p = src + (long)b * CHW + (long)ch * CH;
    int tid = threadIdx.x;
    float s = 0.f, q = 0.f;
    for (int i = tid; i < CH; i += 256) { float v = p[i]; s += v; q += v * v; }
    __shared__ float shs[8], shq[8];
#pragma unroll
    for (int o = 16; o; o >>= 1) {
        s += __shfl_xor_sync(0xffffffffu, s, o);
        q += __shfl_xor_sync(0xffffffffu, q, o);
    }
    if ((tid & 31) == 0) { shs[tid >> 5] = s; shq[tid >> 5] = q; }
    __syncthreads();
    if (tid < 8) {
        s = shs[tid]; q = shq[tid];
#pragma unroll
        for (int o = 4; o; o >>= 1) {
            s += __shfl_xor_sync(0xffu, s, o);
            q += __shfl_xor_sync(0xffu, q, o);
        }
        if (tid == 0) {
            g_part[(b * 64 + ch) * 2 + 0] = s;
            g_part[(b * 64 + ch) * 2 + 1] = q;
        }
    }
}

__global__ void ln_final_kernel() {
    int b = blockIdx.x;
    int tid = threadIdx.x;  // 32 threads
    float s = 0.f, q = 0.f;
    for (int i = tid; i < 64; i += 32) {
        s += g_part[(b * 64 + i) * 2 + 0];
        q += g_part[(b * 64 + i) * 2 + 1];
    }
#pragma unroll
    for (int o = 16; o; o >>= 1) {
        s += __shfl_xor_sync(0xffffffffu, s, o);
        q += __shfl_xor_sync(0xffffffffu, q, o);
    }
    if (tid == 0) {
        float mu = s / (float)CHW;
        float var = q / (float)CHW - mu * mu;
        g_stats[2 * b]     = mu;
        g_stats[2 * b + 1] = rsqrtf(var + 1e-5f);
    }
}

// ================= softmax (row-wise, in place) =================
__global__ void __launch_bounds__(256)
softmax_kernel(float* __restrict__ S, int L) {
    long row = blockIdx.x;
    float* p = S + row * (long)L;
    int tid = threadIdx.x;
    __shared__ float sh[8];

    float mx = -3.4e38f;
    for (int i = tid; i < L; i += 256) mx = fmaxf(mx, p[i]);
#pragma unroll
    for (int o = 16; o; o >>= 1) mx = fmaxf(mx, __shfl_xor_sync(0xffffffffu, mx, o));
    if ((tid & 31) == 0) sh[tid >> 5] = mx;
    __syncthreads();
    if (tid < 8) {
        float v = sh[tid];
#pragma unroll
        for (int o = 4; o; o >>= 1) v = fmaxf(v, __shfl_xor_sync(0xffu, v, o));
        if (tid == 0) sh[0] = v;
    }
    __syncthreads();
    mx = sh[0];
    __syncthreads();

    float s = 0.f;
    for (int i = tid; i < L; i += 256) { float e = __expf(p[i] - mx); p[i] = e; s += e; }
#pragma unroll
    for (int o = 16; o; o >>= 1) s += __shfl_xor_sync(0xffffffffu, s, o);
    if ((tid & 31) == 0) sh[tid >> 5] = s;
    __syncthreads();
    if (tid < 8) {
        float v = sh[tid];
#pragma unroll
        for (int o = 4; o; o >>= 1) v += __shfl_xor_sync(0xffu, v, o);
        if (tid == 0) sh[0] = v;
    }
    __syncthreads();
    float inv = 1.f / sh[0];
    for (int i = tid; i < L; i += 256) p[i] *= inv;
}

// ================= patchify: dst[b,n,d] = src[b, c0+c, h, w] =================
__global__ void __launch_bounds__(256)
patchify_kernel(const float* __restrict__ src, float* __restrict__ dst, int c0, int P) {
    long i = (long)blockIdx.x * blockDim.x + threadIdx.x;
    const long per_b = 64L * HW;                  // Nw*D = 262144
    long total = (long)NB * per_b;
    if (i >= total) return;
    int ow = 64 / P;
    int D = 64 * P * P;
    int Nw = ow * ow;
    int d = (int)(i % D);
    long t = i / D;
    int n = (int)(t % Nw);
    int b = (int)(t / Nw);
    int c  = d / (P * P);
    int r  = d - c * (P * P);
    int py = r / P, px = r - (r / P) * P;
    int iY = n / ow, jX = n - iY * ow;
    int h = iY * P + py, w = jX * P + px;
    dst[i] = src[((long)b * NC + c0 + c) * HW + h * 64 + w];
}

// ================= unpatch + residual add -> mid =================
__global__ void __launch_bounds__(256)
unpatch_add_kernel(const float* __restrict__ x) {
    long i = (long)blockIdx.x * blockDim.x + threadIdx.x;
    long total = (long)NB * CHW;
    if (i >= total) return;
    int p = (int)(i & 4095);
    int c = (int)((i >> 12) & 127);
    int b = (int)(i >> 19);
    int h = p >> 6, w = p & 63;
    float y;
    if (c < 64) {   // scale 1: P=2, Nw=1024, D=256
        int n = (h >> 1) * 32 + (w >> 1);
        int d = c * 4 + (h & 1) * 2 + (w & 1);
        y = g_y1[((long)b * 1024 + n) * 256 + d];
    } else {        // scale 2: P=4, Nw=256, D=1024
        int n = (h >> 2) * 16 + (w >> 2);
        int d = (c - 64) * 16 + (h & 3) * 4 + (w & 3);
        y = g_y2[((long)b * 256 + n) * 1024 + d];
    }
    g_mid[i] = x[i] + y;
}

// ================= host side =================
static void launch_gemm_nn(const float* A, int lda, long sA,
                           const float* B, long sB, float* Cm, long sC,
                           int M, int N, int K, int mode,
                           const float* bias = nullptr, const float* t0 = nullptr,
                           const float* gamma = nullptr, const float* betaS = nullptr,
                           const float* stats = nullptr) {
    dim3 grid(N / 64, M / 64, NB);
    gemm_nn_kernel<<<grid, 256>>>(A, lda, sA, B, sB, Cm, sC, N, K, mode,
                                  bias, t0, gamma, betaS, stats);
}

extern "C" void kernel_launch(void* const* d_in, const int* in_sizes, int n_in,
                              void* d_out, int out_size) {
    const float* x    = (const float*)d_in[0];
    const float* edge = (const float*)d_in[1];
    const float* seg  = (const float*)d_in[2];
    const float* pe   = (const float*)d_in[3];
    const float* ps   = (const float*)d_in[4];
    const float* q_w  = (const float*)d_in[5];
    const float* q_b  = (const float*)d_in[6];
    const float* k_w  = (const float*)d_in[7];
    const float* k_b  = (const float*)d_in[8];
    const float* v_w  = (const float*)d_in[9];
    const float* v_b  = (const float*)d_in[10];
    const float* d1_embed_w = (const float*)d_in[11];
    const float* d1_embed_b = (const float*)d_in[12];
    const float* d1_scale_w = (const float*)d_in[13];
    const float* d1_scale_b = (const float*)d_in[14];
    const float* d1_bias_w  = (const float*)d_in[15];
    const float* d1_bias_b  = (const float*)d_in[16];
    const float* d2_embed_w = (const float*)d_in[17];
    const float* d2_embed_b = (const float*)d_in[18];
    const float* d2_scale_w = (const float*)d_in[19];
    const float* d2_scale_b = (const float*)d_in[20];
    const float* d2_bias_w  = (const float*)d_in[21];
    const float* d2_bias_b  = (const float*)d_in[22];
    const float* sc_w  = (const float*)d_in[23];
    const float* sc_b  = (const float*)d_in[24];
    const float* bi1_w = (const float*)d_in[25];
    const float* bi1_b = (const float*)d_in[26];
    const float* bi2_w = (const float*)d_in[27];
    const float* bi2_b = (const float*)d_in[28];
    float* out = (float*)d_out;

    float *aux_, *a_, *gamma_, *betaS_, *t0_, *q_, *k_, *v_, *mid_, *o_, *gf_, *tmp_;
    float *qp1_, *kp1_, *vp1_, *qp2_, *kp2_, *vp2_, *s1_, *s2_, *y1_, *y2_, *stats_;
    cudaGetSymbolAddress((void**)&aux_,   g_aux);
    cudaGetSymbolAddress((void**)&a_,     g_a);
    cudaGetSymbolAddress((void**)&gamma_, g_gamma);
    cudaGetSymbolAddress((void**)&betaS_, g_betaS);
    cudaGetSymbolAddress((void**)&t0_,    g_t0);
    cudaGetSymbolAddress((void**)&q_,     g_q);
    cudaGetSymbolAddress((void**)&k_,     g_k);
    cudaGetSymbolAddress((void**)&v_,     g_v);
    cudaGetSymbolAddress((void**)&mid_,   g_mid);
    cudaGetSymbolAddress((void**)&o_,     g_o);
    cudaGetSymbolAddress((void**)&gf_,    g_gf);
    cudaGetSymbolAddress((void**)&tmp_,   g_tmp);
    cudaGetSymbolAddress((void**)&qp1_,   g_qp1);
    cudaGetSymbolAddress((void**)&kp1_,   g_kp1);
    cudaGetSymbolAddress((void**)&vp1_,   g_vp1);
    cudaGetSymbolAddress((void**)&qp2_,   g_qp2);
    cudaGetSymbolAddress((void**)&kp2_,   g_kp2);
    cudaGetSymbolAddress((void**)&vp2_,   g_vp2);
    cudaGetSymbolAddress((void**)&s1_,    g_s1);
    cudaGetSymbolAddress((void**)&s2_,    g_s2);
    cudaGetSymbolAddress((void**)&y1_,    g_y1);
    cudaGetSymbolAddress((void**)&y2_,    g_y2);
    cudaGetSymbolAddress((void**)&stats_, g_stats);

    // 1. aux concat
    {
        long total = (long)NB * AUXC * HW;
        concat_aux_kernel<<<(int)((total + 255) / 256), 256>>>(edge, seg, pe, ps);
    }

    // 2. ADN-1 shared pieces
    launch_gemm_nn(d1_embed_w, AUXC, 0, aux_, (long)AUXC * HW, a_, CHW,
                   NC, HW, AUXC, EP_BIAS, d1_embed_b);
    launch_gemm_nn(d1_scale_w, NC, 0, a_, CHW, gamma_, CHW,
                   NC, HW, NC, EP_BIAS, d1_scale_b);
    launch_gemm_nn(d1_bias_w + NC, 2 * NC, 0, a_, CHW, betaS_, CHW,
                   NC, HW, NC, EP_BIAS, d1_bias_b);

    // 3. q / k / v : conv1x1 -> LN stats -> fused ADN
    const float* tw[3] = { q_w, k_w, v_w };
    const float* tb[3] = { q_b, k_b, v_b };
    float* tout[3] = { q_, k_, v_ };
    for (int t = 0; t < 3; t++) {
        launch_gemm_nn(tw[t], NC, 0, x, CHW, t0_, CHW, NC, HW, NC, EP_BIAS, tb[t]);
        ln_part_kernel<<<dim3(64, NB), 256>>>(t0_);
        ln_final_kernel<<<NB, 32>>>();
        launch_gemm_nn(d1_bias_w, 2 * NC, 0, t0_, CHW, tout[t], CHW,
                       NC, HW, NC, EP_ADN, nullptr, t0_, gamma_, betaS_, stats_);
    }

    // 4. patchify (scale1: c 0..63, P=2 ; scale2: c 64..127, P=4)
    {
        int blocks = (int)(((long)NB * 64 * HW + 255) / 256);
        patchify_kernel<<<blocks, 256>>>(q_, qp1_, 0, 2);
        patchify_kernel<<<blocks, 256>>>(k_, kp1_, 0, 2);
        patchify_kernel<<<blocks, 256>>>(v_, vp1_, 0, 2);
        patchify_kernel<<<blocks, 256>>>(q_, qp2_, 64, 4);
        patchify_kernel<<<blocks, 256>>>(k_, kp2_, 64, 4);
        patchify_kernel<<<blocks, 256>>>(v_, vp2_, 64, 4);
    }

    // 5. attention scale 1: N=1024, d=256
    gemm_nt_kernel<<<dim3(16, 16, NB), 256>>>(qp1_, 1024L * 256, kp1_, 1024L * 256,
                                              s1_, 1024L * 1024, 1024, 256, 0.0625f);
    softmax_kernel<<<NB * 1024, 256>>>(s1_, 1024);
    launch_gemm_nn(s1_, 1024, 1024L * 1024, vp1_, 1024L * 256, y1_, 1024L * 256,
                   1024, 256, 1024, EP_NONE);

    // 6. attention scale 2: N=256, d=1024
    gemm_nt_kernel<<<dim3(4, 4, NB), 256>>>(qp2_, 256L * 1024, kp2_, 256L * 1024,
                                            s2_, 256L * 256, 256, 1024, 0.03125f);
    softmax_kernel<<<NB * 256, 256>>>(s2_, 256);
    launch_gemm_nn(s2_, 256, 256L * 256, vp2_, 256L * 1024, y2_, 256L * 1024,
                   256, 1024, 256, EP_NONE);

    // 7. mid = x + unpatch(y1,y2)
    unpatch_add_kernel<<<(int)(((long)NB * CHW + 255) / 256), 256>>>(x);

    // 8. ADN-2 (t = mid)
    launch_gemm_nn(d2_embed_w, AUXC, 0, aux_, (long)AUXC * HW, a_, CHW,
                   NC, HW, AUXC, EP_BIAS, d2_embed_b);
    launch_gemm_nn(d2_scale_w, NC, 0, a_, CHW, gamma_, CHW,
                   NC, HW, NC, EP_BIAS, d2_scale_b);
    launch_gemm_nn(d2_bias_w + NC, 2 * NC, 0, a_, CHW, betaS_, CHW,
                   NC, HW, NC, EP_BIAS, d2_bias_b);
    ln_part_kernel<<<dim3(64, NB), 256>>>(mid_);
    ln_final_kernel<<<NB, 32>>>();
    launch_gemm_nn(d2_bias_w, 2 * NC, 0, mid_, CHW, o_, CHW,
                   NC, HW, NC, EP_ADN, nullptr, mid_, gamma_, betaS_, stats_);

    // 9. conv3x3 chain
    conv3x3_kernel<<<dim3(64, 2, NB), 256>>>(sc_w,  o_,   gf_,  sc_b,  1, EP_TANH,  nullptr, nullptr);
    conv3x3_kernel<<<dim3(64, 2, NB), 256>>>(bi1_w, o_,   tmp_, bi1_b, 2, EP_GELU,  nullptr, nullptr);
    conv3x3_kernel<<<dim3(64, 2, NB), 256>>>(bi2_w, tmp_, out,  bi2_b, 1, EP_FINAL, mid_, gf_);
}

// round 2
// speedup vs baseline: 1.5286x; 1.5286x over previous
#include <cuda_runtime.h>
#include <math.h>
#include <stdint.h>

// ---------------- problem constants ----------------
#define NB 16
#define NC 128
#define HW 4096           // 64*64
#define CHW (NC*HW)       // 524288
#define AUXC 277

// ---------------- scratch (device globals; no allocs) ----------------
__device__ float g_aux  [NB*AUXC*HW];
__device__ float g_a    [NB*CHW];
__device__ float g_gamma[NB*CHW];
__device__ float g_betaS[NB*CHW];
__device__ float g_t0   [NB*CHW];
__device__ float g_q    [NB*CHW];
__device__ float g_k    [NB*CHW];
__device__ float g_v    [NB*CHW];
__device__ float g_mid  [NB*CHW];
__device__ float g_o    [NB*CHW];
__device__ float g_gf   [NB*CHW];
__device__ float g_tmp  [NB*CHW];
__device__ float g_qp1  [NB*1024*256];
__device__ float g_kp1  [NB*1024*256];
__device__ float g_vp1  [NB*1024*256];
__device__ float g_qp2  [NB*256*1024];
__device__ float g_kp2  [NB*256*1024];
__device__ float g_vp2  [NB*256*1024];
__device__ float g_s1   [NB*1024L*1024];
__device__ float g_s2   [NB*256*256];
__device__ float g_y1   [NB*1024*256];
__device__ float g_y2   [NB*256*1024];
__device__ float g_stats[NB*2];
__device__ float g_part [NB*64*2];

// ---------------- epilogue modes ----------------
#define EP_BIAS  0
#define EP_ADN   1
#define EP_NONE  2
#define EP_TANH  3
#define EP_GELU  4
#define EP_FINAL 5

// ---------------- tf32 helpers ----------------
__device__ __forceinline__ float to_tf32(float x) {
    uint32_t o;
    asm("cvt.rna.tf32.f32 %0, %1;" : "=r"(o) : "f"(x));
    return __uint_as_float(o);
}

__device__ __forceinline__ void mma_tf32(float& c0, float& c1, float& c2, float& c3,
                                         float a0, float a1, float a2, float a3,
                                         float b0, float b1) {
    asm volatile(
        "mma.sync.aligned.m16n8k8.row.col.f32.tf32.tf32.f32 "
        "{%0,%1,%2,%3}, {%4,%5,%6,%7}, {%8,%9}, {%0,%1,%2,%3};"
        : "+f"(c0), "+f"(c1), "+f"(c2), "+f"(c3)
        : "r"(__float_as_uint(a0)), "r"(__float_as_uint(a1)),
          "r"(__float_as_uint(a2)), "r"(__float_as_uint(a3)),
          "r"(__float_as_uint(b0)), "r"(__float_as_uint(b1)));
}

// shared layout strides (floats)
#define SA_LD 20    // [128][20]  row-major rows (conflict-free fragment loads)
#define SBK_LD 136  // [16][136]  k-major rows (nn / conv B)

// ================= concat aux =================
__global__ void __launch_bounds__(256)
concat_aux_kernel(const float* __restrict__ edge, const float* __restrict__ seg,
                  const float* __restrict__ pe,   const float* __restrict__ ps) {
    long i = (long)blockIdx.x * blockDim.x + threadIdx.x;
    long total = (long)NB * AUXC * HW;
    if (i >= total) return;
    int p = (int)(i % HW);
    long t = i / HW;
    int c = (int)(t % AUXC);
    int b = (int)(t / AUXC);
    float v;
    if (c < 128)       v = edge[((long)b*128 + c)      * HW + p];
    else if (c < 256)  v = seg [((long)b*128 + (c-128))* HW + p];
    else if (c == 256) v = pe  [(long)b * HW + p];
    else               v = ps  [((long)b*20 + (c-257)) * HW + p];
    g_aux[i] = v;
}

// ================= generic epilogue =================
__device__ __forceinline__ float apply_ep(float v, int mode, float scale,
                                          int m, long idx, long gidx,
                                          const float* bias, const float* t0,
                                          const float* gamma, const float* betaS,
                                          float mu, float rs) {
    if (mode == EP_BIAS) {
        return v + bias[m];
    } else if (mode == EP_ADN) {
        return (t0[gidx] - mu) * rs * gamma[gidx] + v + betaS[gidx];
    } else {
        return v * scale;
    }
}

// ================= tensor-core GEMM =================
// C[m,n] = A[m,k] * B[k,n]  (TRANSB=false, B row-major [K][N], ldb)
// C[m,n] = A[m,k] * B[n,k]  (TRANSB=true,  B row-major [N][K], ldb)
// Block tile 128x128, 8 warps of 64x32, Kt=16.
template<bool TRANSB>
__global__ void __launch_bounds__(256)
tc_gemm_kernel(const float* __restrict__ A, int lda, long sA_,
               const float* __restrict__ Bm, int ldb, long sB_,
               float* __restrict__ Cm, long sC_,
               int N, int K, int mode, float scale,
               const float* __restrict__ bias,
               const float* __restrict__ t0,
               const float* __restrict__ gamma,
               const float* __restrict__ betaS,
               const float* __restrict__ stats)
{
    int bb = blockIdx.z;
    int n0 = blockIdx.x * 128;
    int m0 = blockIdx.y * 128;
    const float* Ap = A  + (long)bb * sA_;
    const float* Bp = Bm + (long)bb * sB_;
    float* Cp       = Cm + (long)bb * sC_;

    __shared__ float sA[128 * SA_LD];
    __shared__ float sB[TRANSB ? 128 * SA_LD : 16 * SBK_LD];

    int tid  = threadIdx.x;
    int lane = tid & 31;
    int warp = tid >> 5;
    int wm = (warp >> 2) * 64;
    int wn = (warp & 3) * 32;
    int r    = lane >> 2;
    int cg   = lane & 3;

    float acc[4][4][4];
#pragma unroll
    for (int i = 0; i < 4; i++)
#pragma unroll
        for (int j = 0; j < 4; j++)
#pragma unroll
            for (int q = 0; q < 4; q++) acc[i][j][q] = 0.f;

    for (int kt = 0; kt < K; kt += 16) {
        // ---- load A tile [128 rows][16 k] ----
        {
            int row = tid >> 1;                 // 0..127
            int kk0 = (tid & 1) * 8;
            const float* ar = Ap + (long)(m0 + row) * lda;
#pragma unroll
            for (int i = 0; i < 8; i++) {
                int k = kt + kk0 + i;
                float v = (k < K) ? ar[k] : 0.f;
                sA[row * SA_LD + kk0 + i] = to_tf32(v);
            }
        }
        // ---- load B tile ----
        if (TRANSB) {
            int row = tid >> 1;                 // n-row 0..127
            int kk0 = (tid & 1) * 8;
            const float* br = Bp + (long)(n0 + row) * ldb;
#pragma unroll
            for (int i = 0; i < 8; i++) {
                int k = kt + kk0 + i;
                float v = (k < K) ? br[k] : 0.f;
                sB[row * SA_LD + kk0 + i] = to_tf32(v);
            }
        } else {
#pragma unroll
            for (int i = 0; i < 2; i++) {
                int e4 = tid + i * 256;         // 0..511
                int row = e4 >> 5;              // k-row 0..15
                int c4  = e4 & 31;
                int k = kt + row;
                float4 v = make_float4(0.f, 0.f, 0.f, 0.f);
                if (k < K)
                    v = *(const float4*)(Bp + (long)k * ldb + n0 + c4 * 4);
                float* d = &sB[row * SBK_LD + c4 * 4];
                d[0] = to_tf32(v.x); d[1] = to_tf32(v.y);
                d[2] = to_tf32(v.z); d[3] = to_tf32(v.w);
            }
        }
        __syncthreads();

#pragma unroll
        for (int ks = 0; ks < 16; ks += 8) {
            float af[4][4];
#pragma unroll
            for (int mt = 0; mt < 4; mt++) {
                int base = wm + mt * 16;
                af[mt][0] = sA[(base + r)     * SA_LD + ks + cg];
                af[mt][1] = sA[(base + r + 8) * SA_LD + ks + cg];
                af[mt][2] = sA[(base + r)     * SA_LD + ks + cg + 4];
                af[mt][3] = sA[(base + r + 8) * SA_LD + ks + cg + 4];
            }
            float bf[4][2];
#pragma unroll
            for (int nt = 0; nt < 4; nt++) {
                if (TRANSB) {
                    int nrow = wn + nt * 8 + r;
                    bf[nt][0] = sB[nrow * SA_LD + ks + cg];
                    bf[nt][1] = sB[nrow * SA_LD + ks + cg + 4];
                } else {
                    int ncol = wn + nt * 8 + r;
                    bf[nt][0] = sB[(ks + cg)     * SBK_LD + ncol];
                    bf[nt][1] = sB[(ks + cg + 4) * SBK_LD + ncol];
                }
            }
#pragma unroll
            for (int mt = 0; mt < 4; mt++)
#pragma unroll
                for (int nt = 0; nt < 4; nt++)
                    mma_tf32(acc[mt][nt][0], acc[mt][nt][1], acc[mt][nt][2], acc[mt][nt][3],
                             af[mt][0], af[mt][1], af[mt][2], af[mt][3],
                             bf[nt][0], bf[nt][1]);
        }
        __syncthreads();
    }

    // ---- epilogue ----
    float mu = 0.f, rs = 0.f;
    if (mode == EP_ADN) { mu = stats[2 * bb]; rs = stats[2 * bb + 1]; }
#pragma unroll
    for (int mt = 0; mt < 4; mt++) {
#pragma unroll
        for (int nt = 0; nt < 4; nt++) {
            int m1 = m0 + wm + mt * 16 + r;
            int m2 = m1 + 8;
            int nn = n0 + wn + nt * 8 + cg * 2;
            long i1 = (long)m1 * N + nn;
            long i2 = (long)m2 * N + nn;
            long base = (long)bb * sC_;
            Cp[i1]     = apply_ep(acc[mt][nt][0], mode, scale, m1, i1, base + i1,     bias, t0, gamma, betaS, mu, rs);
            Cp[i1 + 1] = apply_ep(acc[mt][nt][1], mode, scale, m1, i1 + 1, base + i1 + 1, bias, t0, gamma, betaS, mu, rs);
            Cp[i2]     = apply_ep(acc[mt][nt][2], mode, scale, m2, i2, base + i2,     bias, t0, gamma, betaS, mu, rs);
            Cp[i2 + 1] = apply_ep(acc[mt][nt][3], mode, scale, m2, i2 + 1, base + i2 + 1, bias, t0, gamma, betaS, mu, rs);
        }
    }
}

// ================= tensor-core conv3x3 implicit GEMM: M=128, N=4096, K=1152 =================
__global__ void __launch_bounds__(256)
tc_conv3x3_kernel(const float* __restrict__ Wt,  // [128][1152]
                  const float* __restrict__ X,   // [B,128,64,64]
                  float* __restrict__ Cm,
                  const float* __restrict__ bias,
                  int dil, int mode,
                  const float* __restrict__ mid,
                  const float* __restrict__ gf)
{
    const int K = 1152, N = HW;
    int bb = blockIdx.z;
    int n0 = blockIdx.x * 128;
    const int m0 = 0;
    const float* Xp = X + (long)bb * CHW;
    float* Cp = Cm + (long)bb * CHW;

    __shared__ float sA[128 * SA_LD];
    __shared__ float sB[16 * SBK_LD];

    int tid  = threadIdx.x;
    int lane = tid & 31;
    int warp = tid >> 5;
    int wm = (warp >> 2) * 64;
    int wn = (warp & 3) * 32;
    int r  = lane >> 2;
    int cg = lane & 3;

    float acc[4][4][4];
#pragma unroll
    for (int i = 0; i < 4; i++)
#pragma unroll
        for (int j = 0; j < 4; j++)
#pragma unroll
            for (int q = 0; q < 4; q++) acc[i][j][q] = 0.f;

    for (int kt = 0; kt < K; kt += 16) {
        {
            int row = tid >> 1;
            int kk0 = (tid & 1) * 8;
            const float* ar = Wt + (long)(m0 + row) * K;
#pragma unroll
            for (int i = 0; i < 8; i++)
                sA[row * SA_LD + kk0 + i] = to_tf32(ar[kt + kk0 + i]);
        }
        {
#pragma unroll
            for (int i = 0; i < 8; i++) {
                int e = tid + i * 256;          // 0..2047
                int kk = e >> 7;                // 0..15
                int n  = e & 127;
                int k = kt + kk;
                int c = k / 9;
                int t = k - c * 9;
                int dy = (t / 3 - 1) * dil;
                int dx = (t % 3 - 1) * dil;
                int p = n0 + n;
                int h = (p >> 6) + dy;
                int w = (p & 63) + dx;
                float v = 0.f;
                if ((unsigned)h < 64u && (unsigned)w < 64u)
                    v = Xp[(long)c * HW + h * 64 + w];
                sB[kk * SBK_LD + n] = to_tf32(v);
            }
        }
        __syncthreads();

#pragma unroll
        for (int ks = 0; ks < 16; ks += 8) {
            float af[4][4];
#pragma unroll
            for (int mt = 0; mt < 4; mt++) {
                int base = wm + mt * 16;
                af[mt][0] = sA[(base + r)     * SA_LD + ks + cg];
                af[mt][1] = sA[(base + r + 8) * SA_LD + ks + cg];
                af[mt][2] = sA[(base + r)     * SA_LD + ks + cg + 4];
                af[mt][3] = sA[(base + r + 8) * SA_LD + ks + cg + 4];
            }
            float bf[4][2];
#pragma unroll
            for (int nt = 0; nt < 4; nt++) {
                int ncol = wn + nt * 8 + r;
                bf[nt][0] = sB[(ks + cg)     * SBK_LD + ncol];
                bf[nt][1] = sB[(ks + cg + 4) * SBK_LD + ncol];
            }
#pragma unroll
            for (int mt = 0; mt < 4; mt++)
#pragma unroll
                for (int nt = 0; nt < 4; nt++)
                    mma_tf32(acc[mt][nt][0], acc[mt][nt][1], acc[mt][nt][2], acc[mt][nt][3],
                             af[mt][0], af[mt][1], af[mt][2], af[mt][3],
                             bf[nt][0], bf[nt][1]);
        }
        __syncthreads();
    }

#pragma unroll
    for (int mt = 0; mt < 4; mt++) {
#pragma unroll
        for (int nt = 0; nt < 4; nt++) {
#pragma unroll
            for (int half = 0; half < 2; half++) {
                int m = m0 + wm + mt * 16 + r + half * 8;
                float bv = bias[m];
#pragma unroll
                for (int q = 0; q < 2; q++) {
                    int n = n0 + wn + nt * 8 + cg * 2 + q;
                    long idx = (long)m * N + n;
                    float v = acc[mt][nt][half * 2 + q] + bv;
                    if (mode == EP_TANH) {
                        v = tanhf(v);
                    } else if (mode == EP_GELU) {
                        v = 0.5f * v * (1.f + erff(v * 0.70710678118654752f));
                    } else if (mode == EP_FINAL) {
                        long g = (long)bb * CHW + idx;
                        v = mid[g] * gf[g] + v;
                    }
                    Cp[idx] = v;
                }
            }
        }
    }
}

// ================= LayerNorm stats (2-stage, deterministic) =================
__global__ void __launch_bounds__(256)
ln_part_kernel(const float* __restrict__ src) {
    int b = blockIdx.y, ch = blockIdx.x;
    const int CH = CHW / 64;
    const float* p = src + (long)b * CHW + (long)ch * CH;
    int tid = threadIdx.x;
    float s = 0.f, q = 0.f;
    for (int i = tid; i < CH; i += 256) { float v = p[i]; s += v; q += v * v; }
    __shared__ float shs[8], shq[8];
#pragma unroll
    for (int o = 16; o; o >>= 1) {
        s += __shfl_xor_sync(0xffffffffu, s, o);
        q += __shfl_xor_sync(0xffffffffu, q, o);
    }
    if ((tid & 31) == 0) { shs[tid >> 5] = s; shq[tid >> 5] = q; }
    __syncthreads();
    if (tid < 8) {
        s = shs[tid]; q = shq[tid];
#pragma unroll
        for (int o = 4; o; o >>= 1) {
            s += __shfl_xor_sync(0xffu, s, o);
            q += __shfl_xor_sync(0xffu, q, o);
        }
        if (tid == 0) {
            g_part[(b * 64 + ch) * 2 + 0] = s;
            g_part[(b * 64 + ch) * 2 + 1] = q;
        }
    }
}

__global__ void ln_final_kernel() {
    int b = blockIdx.x;
    int tid = threadIdx.x;
    float s = 0.f, q = 0.f;
    for (int i = tid; i < 64; i += 32) {
        s += g_part[(b * 64 + i) * 2 + 0];
        q += g_part[(b * 64 + i) * 2 + 1];
    }
#pragma unroll
    for (int o = 16; o; o >>= 1) {
        s += __shfl_xor_sync(0xffffffffu, s, o);
        q += __shfl_xor_sync(0xffffffffu, q, o);
    }
    if (tid == 0) {
        float mu = s / (float)CHW;
        float var = q / (float)CHW - mu * mu;
        g_stats[2 * b]     = mu;
        g_stats[2 * b + 1] = rsqrtf(var + 1e-5f);
    }
}

// ================= softmax =================
__global__ void __launch_bounds__(256)
softmax_kernel(float* __restrict__ S, int L) {
    long row = blockIdx.x;
    float* p = S + row * (long)L;
    int tid = threadIdx.x;
    __shared__ float sh[8];

    float mx = -3.4e38f;
    for (int i = tid; i < L; i += 256) mx = fmaxf(mx, p[i]);
#pragma unroll
    for (int o = 16; o; o >>= 1) mx = fmaxf(mx, __shfl_xor_sync(0xffffffffu, mx, o));
    if ((tid & 31) == 0) sh[tid >> 5] = mx;
    __syncthreads();
    if (tid < 8) {
        float v = sh[tid];
#pragma unroll
        for (int o = 4; o; o >>= 1) v = fmaxf(v, __shfl_xor_sync(0xffu, v, o));
        if (tid == 0) sh[0] = v;
    }
    __syncthreads();
    mx = sh[0];
    __syncthreads();

    float s = 0.f;
    for (int i = tid; i < L; i += 256) { float e = __expf(p[i] - mx); p[i] = e; s += e; }
#pragma unroll
    for (int o = 16; o; o >>= 1) s += __shfl_xor_sync(0xffffffffu, s, o);
    if ((tid & 31) == 0) sh[tid >> 5] = s;
    __syncthreads();
    if (tid < 8) {
        float v = sh[tid];
#pragma unroll
        for (int o = 4; o; o >>= 1) v += __shfl_xor_sync(0xffu, v, o);
        if (tid == 0) sh[0] = v;
    }
    __syncthreads();
    float inv = 1.f / sh[0];
    for (int i = tid; i < L; i += 256) p[i] *= inv;
}

// ================= patchify =================
__global__ void __launch_bounds__(256)
patchify_kernel(const float* __restrict__ src, float* __restrict__ dst, int c0, int P) {
    long i = (long)blockIdx.x * blockDim.x + threadIdx.x;
    const long per_b = 64L * HW;
    long total = (long)NB * per_b;
    if (i >= total) return;
    int ow = 64 / P;
    int D = 64 * P * P;
    int Nw = ow * ow;
    int d = (int)(i % D);
    long t = i / D;
    int n = (int)(t % Nw);
    int b = (int)(t / Nw);
    int c  = d / (P * P);
    int rr = d - c * (P * P);
    int py = rr / P, px = rr - (rr / P) * P;
    int iY = n / ow, jX = n - iY * ow;
    int h = iY * P + py, w = jX * P + px;
    dst[i] = src[((long)b * NC + c0 + c) * HW + h * 64 + w];
}

// ================= unpatch + residual =================
__global__ void __launch_bounds__(256)
unpatch_add_kernel(const float* __restrict__ x) {
    long i = (long)blockIdx.x * blockDim.x + threadIdx.x;
    long total = (long)NB * CHW;
    if (i >= total) return;
    int p = (int)(i & 4095);
    int c = (int)((i >> 12) & 127);
    int b = (int)(i >> 19);
    int h = p >> 6, w = p & 63;
    float y;
    if (c < 64) {
        int n = (h >> 1) * 32 + (w >> 1);
        int d = c * 4 + (h & 1) * 2 + (w & 1);
        y = g_y1[((long)b * 1024 + n) * 256 + d];
    } else {
        int n = (h >> 2) * 16 + (w >> 2);
        int d = (c - 64) * 16 + (h & 3) * 4 + (w & 3);
        y = g_y2[((long)b * 256 + n) * 1024 + d];
    }
    g_mid[i] = x[i] + y;
}

// ================= host side =================
static void tc_nn(const float* A, int lda, long sA,
                  const float* B, int ldb, long sB, float* C, long sC,
                  int M, int N, int K, int mode, float scale = 1.f,
                  const float* bias = nullptr, const float* t0 = nullptr,
                  const float* gamma = nullptr, const float* betaS = nullptr,
                  const float* stats = nullptr) {
    dim3 grid(N / 128, M / 128, NB);
    tc_gemm_kernel<false><<<grid, 256>>>(A, lda, sA, B, ldb, sB, C, sC, N, K,
                                         mode, scale, bias, t0, gamma, betaS, stats);
}

static void tc_nt(const float* A, int lda, long sA,
                  const float* B, int ldb, long sB, float* C, long sC,
                  int M, int N, int K, float scale) {
    dim3 grid(N / 128, M / 128, NB);
    tc_gemm_kernel<true><<<grid, 256>>>(A, lda, sA, B, ldb, sB, C, sC, N, K,
                                        EP_NONE, scale, nullptr, nullptr, nullptr, nullptr, nullptr);
}

extern "C" void kernel_launch(void* const* d_in, const int* in_sizes, int n_in,
                              void* d_out, int out_size) {
    const float* x    = (const float*)d_in[0];
    const float* edge = (const float*)d_in[1];
    const float* seg  = (const float*)d_in[2];
    const float* pe   = (const float*)d_in[3];
    const float* ps   = (const float*)d_in[4];
    const float* q_w  = (const float*)d_in[5];
    const float* q_b  = (const float*)d_in[6];
    const float* k_w  = (const float*)d_in[7];
    const float* k_b  = (const float*)d_in[8];
    const float* v_w  = (const float*)d_in[9];
    const float* v_b  = (const float*)d_in[10];
    const float* d1_embed_w = (const float*)d_in[11];
    const float* d1_embed_b = (const float*)d_in[12];
    const float* d1_scale_w = (const float*)d_in[13];
    const float* d1_scale_b = (const float*)d_in[14];
    const float* d1_bias_w  = (const float*)d_in[15];
    const float* d1_bias_b  = (const float*)d_in[16];
    const float* d2_embed_w = (const float*)d_in[17];
    const float* d2_embed_b = (const float*)d_in[18];
    const float* d2_scale_w = (const float*)d_in[19];
    const float* d2_scale_b = (const float*)d_in[20];
    const float* d2_bias_w  = (const float*)d_in[21];
    const float* d2_bias_b  = (const float*)d_in[22];
    const float* sc_w  = (const float*)d_in[23];
    const float* sc_b  = (const float*)d_in[24];
    const float* bi1_w = (const float*)d_in[25];
    const float* bi1_b = (const float*)d_in[26];
    const float* bi2_w = (const float*)d_in[27];
    const float* bi2_b = (const float*)d_in[28];
    float* out = (float*)d_out;

    float *aux_, *a_, *gamma_, *betaS_, *t0_, *q_, *k_, *v_, *mid_, *o_, *gf_, *tmp_;
    float *qp1_, *kp1_, *vp1_, *qp2_, *kp2_, *vp2_, *s1_, *s2_, *y1_, *y2_, *stats_;
    cudaGetSymbolAddress((void**)&aux_,   g_aux);
    cudaGetSymbolAddress((void**)&a_,     g_a);
    cudaGetSymbolAddress((void**)&gamma_, g_gamma);
    cudaGetSymbolAddress((void**)&betaS_, g_betaS);
    cudaGetSymbolAddress((void**)&t0_,    g_t0);
    cudaGetSymbolAddress((void**)&q_,     g_q);
    cudaGetSymbolAddress((void**)&k_,     g_k);
    cudaGetSymbolAddress((void**)&v_,     g_v);
    cudaGetSymbolAddress((void**)&mid_,   g_mid);
    cudaGetSymbolAddress((void**)&o_,     g_o);
    cudaGetSymbolAddress((void**)&gf_,    g_gf);
    cudaGetSymbolAddress((void**)&tmp_,   g_tmp);
    cudaGetSymbolAddress((void**)&qp1_,   g_qp1);
    cudaGetSymbolAddress((void**)&kp1_,   g_kp1);
    cudaGetSymbolAddress((void**)&vp1_,   g_vp1);
    cudaGetSymbolAddress((void**)&qp2_,   g_qp2);
    cudaGetSymbolAddress((void**)&kp2_,   g_kp2);
    cudaGetSymbolAddress((void**)&vp2_,   g_vp2);
    cudaGetSymbolAddress((void**)&s1_,    g_s1);
    cudaGetSymbolAddress((void**)&s2_,    g_s2);
    cudaGetSymbolAddress((void**)&y1_,    g_y1);
    cudaGetSymbolAddress((void**)&y2_,    g_y2);
    cudaGetSymbolAddress((void**)&stats_, g_stats);

    // 1. aux concat
    {
        long total = (long)NB * AUXC * HW;
        concat_aux_kernel<<<(int)((total + 255) / 256), 256>>>(edge, seg, pe, ps);
    }

    // 2. ADN-1 shared pieces
    tc_nn(d1_embed_w, AUXC, 0, aux_, HW, (long)AUXC * HW, a_, CHW,
          NC, HW, AUXC, EP_BIAS, 1.f, d1_embed_b);
    tc_nn(d1_scale_w, NC, 0, a_, HW, CHW, gamma_, CHW,
          NC, HW, NC, EP_BIAS, 1.f, d1_scale_b);
    tc_nn(d1_bias_w + NC, 2 * NC, 0, a_, HW, CHW, betaS_, CHW,
          NC, HW, NC, EP_BIAS, 1.f, d1_bias_b);

    // 3. q / k / v
    const float* tw[3] = { q_w, k_w, v_w };
    const float* tb[3] = { q_b, k_b, v_b };
    float* tout[3] = { q_, k_, v_ };
    for (int t = 0; t < 3; t++) {
        tc_nn(tw[t], NC, 0, x, HW, CHW, t0_, CHW, NC, HW, NC, EP_BIAS, 1.f, tb[t]);
        ln_part_kernel<<<dim3(64, NB), 256>>>(t0_);
        ln_final_kernel<<<NB, 32>>>();
        tc_nn(d1_bias_w, 2 * NC, 0, t0_, HW, CHW, tout[t], CHW,
              NC, HW, NC, EP_ADN, 1.f, nullptr, t0_, gamma_, betaS_, stats_);
    }

    // 4. patchify
    {
        int blocks = (int)(((long)NB * 64 * HW + 255) / 256);
        patchify_kernel<<<blocks, 256>>>(q_, qp1_, 0, 2);
        patchify_kernel<<<blocks, 256>>>(k_, kp1_, 0, 2);
        patchify_kernel<<<blocks, 256>>>(v_, vp1_, 0, 2);
        patchify_kernel<<<blocks, 256>>>(q_, qp2_, 64, 4);
        patchify_kernel<<<blocks, 256>>>(k_, kp2_, 64, 4);
        patchify_kernel<<<blocks, 256>>>(v_, vp2_, 64, 4);
    }

    // 5. attention scale 1: N=1024 tokens, d=256
    tc_nt(qp1_, 256, 1024L * 256, kp1_, 256, 1024L * 256, s1_, 1024L * 1024,
          1024, 1024, 256, 0.0625f);
    softmax_kernel<<<NB * 1024, 256>>>(s1_, 1024);
    tc_nn(s1_, 1024, 1024L * 1024, vp1_, 256, 1024L * 256, y1_, 1024L * 256,
          1024, 256, 1024, EP_NONE);

    // 6. attention scale 2: N=256 tokens, d=1024
    tc_nt(qp2_, 1024, 256L * 1024, kp2_, 1024, 256L * 1024, s2_, 256L * 256,
          256, 256, 1024, 0.03125f);
    softmax_kernel<<<NB * 256, 256>>>(s2_, 256);
    tc_nn(s2_, 256, 256L * 256, vp2_, 1024, 256L * 1024, y2_, 256L * 1024,
          256, 1024, 256, EP_NONE);

    // 7. mid = x + unpatch(y1,y2)
    unpatch_add_kernel<<<(int)(((long)NB * CHW + 255) / 256), 256>>>(x);

    // 8. ADN-2
    tc_nn(d2_embed_w, AUXC, 0, aux_, HW, (long)AUXC * HW, a_, CHW,
          NC, HW, AUXC, EP_BIAS, 1.f, d2_embed_b);
    tc_nn(d2_scale_w, NC, 0, a_, HW, CHW, gamma_, CHW,
          NC, HW, NC, EP_BIAS, 1.f, d2_scale_b);
    tc_nn(d2_bias_w + NC, 2 * NC, 0, a_, HW, CHW, betaS_, CHW,
          NC, HW, NC, EP_BIAS, 1.f, d2_bias_b);
    ln_part_kernel<<<dim3(64, NB), 256>>>(mid_);
    ln_final_kernel<<<NB, 32>>>();
    tc_nn(d2_bias_w, 2 * NC, 0, mid_, HW, CHW, o_, CHW,
          NC, HW, NC, EP_ADN, 1.f, nullptr, mid_, gamma_, betaS_, stats_);

    // 9. conv3x3 chain
    tc_conv3x3_kernel<<<dim3(32, 1, NB), 256>>>(sc_w,  o_,   gf_,  sc_b,  1, EP_TANH,  nullptr, nullptr);
    tc_conv3x3_kernel<<<dim3(32, 1, NB), 256>>>(bi1_w, o_,   tmp_, bi1_b, 2, EP_GELU,  nullptr, nullptr);
    tc_conv3x3_kernel<<<dim3(32, 1, NB), 256>>>(bi2_w, tmp_, out,  bi2_b, 1, EP_FINAL, mid_, gf_);
}

// round 3
// speedup vs baseline: 2.1650x; 1.4164x over previous
#include <cuda_runtime.h>
#include <math.h>
#include <stdint.h>

// ---------------- problem constants ----------------
#define NB 16
#define NC 128
#define HW 4096           // 64*64
#define CHW (NC*HW)       // 524288
#define AUXC 277

// ---------------- scratch (device globals; no allocs) ----------------
__device__ float g_aux  [NB*AUXC*HW];
__device__ float g_a    [NB*CHW];
__device__ float g_gamma[NB*CHW];
__device__ float g_betaS[NB*CHW];
__device__ float g_t0   [NB*CHW];
__device__ float g_q    [NB*CHW];
__device__ float g_k    [NB*CHW];
__device__ float g_v    [NB*CHW];
__device__ float g_mid  [NB*CHW];
__device__ float g_o    [NB*CHW];
__device__ float g_gf   [NB*CHW];
__device__ float g_tmp  [NB*CHW];
__device__ float g_qp1  [NB*1024*256];
__device__ float g_kp1  [NB*1024*256];
__device__ float g_vp1  [NB*1024*256];
__device__ float g_qp2  [NB*256*1024];
__device__ float g_kp2  [NB*256*1024];
__device__ float g_vp2  [NB*256*1024];
__device__ float g_s1   [NB*1024L*1024];
__device__ float g_s2   [NB*256*256];
__device__ float g_y1   [NB*1024*256];
__device__ float g_y2   [NB*256*1024];
__device__ float g_stats[NB*2];
__device__ float g_part [NB*64*2];

// ---------------- epilogue modes ----------------
#define EP_BIAS  0
#define EP_ADN   1
#define EP_NONE  2
#define EP_TANH  3
#define EP_GELU  4
#define EP_FINAL 5

// ---------------- smem geometry ----------------
#define LDK 36                    // floats per smem row (32 + 4 pad)
#define ROWB (LDK*4)              // 144 bytes per row
#define STAGE_BYTES (256*ROWB)    // A(128 rows) + B(128 rows)
#define SMEM_BYTES (2*STAGE_BYTES)  // 73728

// ---------------- helpers ----------------
__device__ __forceinline__ uint32_t f2tf(float x) {
    uint32_t o;
    asm("cvt.rna.tf32.f32 %0, %1;" : "=r"(o) : "f"(x));
    return o;
}

__device__ __forceinline__ void ldsm_x4(uint32_t& r0, uint32_t& r1, uint32_t& r2, uint32_t& r3,
                                        uint32_t addr) {
    asm volatile("ldmatrix.sync.aligned.m8n8.x4.shared.b16 {%0,%1,%2,%3}, [%4];"
                 : "=r"(r0), "=r"(r1), "=r"(r2), "=r"(r3) : "r"(addr));
}

__device__ __forceinline__ void mma_tf32u(float* c,
                                          uint32_t a0, uint32_t a1, uint32_t a2, uint32_t a3,
                                          uint32_t b0, uint32_t b1) {
    asm volatile(
        "mma.sync.aligned.m16n8k8.row.col.f32.tf32.tf32.f32 "
        "{%0,%1,%2,%3}, {%4,%5,%6,%7}, {%8,%9}, {%0,%1,%2,%3};"
        : "+f"(c[0]), "+f"(c[1]), "+f"(c[2]), "+f"(c[3])
        : "r"(a0), "r"(a1), "r"(a2), "r"(a3), "r"(b0), "r"(b1));
}

// ================= concat aux =================
__global__ void __launch_bounds__(256)
concat_aux_kernel(const float* __restrict__ edge, const float* __restrict__ seg,
                  const float* __restrict__ pe,   const float* __restrict__ ps) {
    long i = (long)blockIdx.x * blockDim.x + threadIdx.x;
    long total = (long)NB * AUXC * HW;
    if (i >= total) return;
    int p = (int)(i % HW);
    long t = i / HW;
    int c = (int)(t % AUXC);
    int b = (int)(t / AUXC);
    float v;
    if (c < 128)       v = edge[((long)b*128 + c)      * HW + p];
    else if (c < 256)  v = seg [((long)b*128 + (c-128))* HW + p];
    else if (c == 256) v = pe  [(long)b * HW + p];
    else               v = ps  [((long)b*20 + (c-257)) * HW + p];
    g_aux[i] = v;
}

// ================= epilogue =================
__device__ __forceinline__ float apply_ep(float v, int mode, float scale,
                                          int m, long gidx,
                                          const float* bias, const float* t0,
                                          const float* gamma, const float* betaS,
                                          const float* mid, const float* gf,
                                          float mu, float rs) {
    if (mode == EP_BIAS)  return v + bias[m];
    if (mode == EP_ADN)   return (t0[gidx] - mu) * rs * gamma[gidx] + v + betaS[gidx];
    if (mode == EP_TANH)  return tanhf(v + bias[m]);
    if (mode == EP_GELU)  { float u = v + bias[m]; return 0.5f * u * (1.f + erff(u * 0.70710678118654752f)); }
    if (mode == EP_FINAL) return mid[gidx] * gf[gidx] + v + bias[m];
    return v * scale;   // EP_NONE
}

// ================= tensor-core GEMM v3 =================
// TRANSB=0, CONV=0 : C[m,n] = A[m,k] * B[k,n]   (B row-major [K][N])
// TRANSB=1         : C[m,n] = A[m,k] * B[n,k]   (B row-major [N][K])
// CONV=1           : implicit conv3x3 GEMM, B gathered from X [128][64][64], K=1152
// CTA tile 128x128, 8 warps of 64x32, Kt=32, 2-stage double buffer, ldmatrix fragments.
template<bool TRANSB, bool CONV>
__global__ void __launch_bounds__(256)
tc_gemm3(const float* __restrict__ A, int lda, long sA_,
         const float* __restrict__ Bm, int ldb, long sB_,
         float* __restrict__ Cm, long sC_,
         int N, int K, int mode, float scale, int dil,
         const float* __restrict__ bias,
         const float* __restrict__ t0,
         const float* __restrict__ gamma,
         const float* __restrict__ betaS,
         const float* __restrict__ stats,
         const float* __restrict__ mid,
         const float* __restrict__ gf)
{
    extern __shared__ float sm[];
    int bb = blockIdx.z;
    int n0 = blockIdx.x * 128;
    int m0 = blockIdx.y * 128;
    const float* Ap = A  + (long)bb * sA_;
    const float* Bp = Bm + (long)bb * sB_;
    float* Cp       = Cm + (long)bb * sC_;

    int tid  = threadIdx.x;
    int lane = tid & 31;
    int warp = tid >> 5;
    int wm = (warp >> 2) * 64;
    int wn = (warp & 3) * 32;

    // loader geometry
    int arow  = tid >> 1;            // 0..127 (m row, or n row if TRANSB)
    int akseg = (tid & 1) * 16;      // 0 / 16
    int bk    = tid & 31;            // k within tile (nn / conv B)
    int bn0   = (tid >> 5) * 16;     // n segment    (nn / conv B)

    // fragment (ldmatrix) per-thread addressing
    uint32_t sbase = (uint32_t)__cvta_generic_to_shared(sm);
    int rowsel = (lane & 7) + ((lane >> 3) & 1) * 8;
    int colsel = ((lane >> 4) & 1) * 16;   // bytes

    bool vecA = ((lda & 3) == 0) && ((K & 3) == 0);

    float ra[16], rb[16];
    float acc[4][4][4] = {};

    // conv: per-thread k decode (constant across tiles except kg)
    int nkt = (K + 31) >> 5;

    for (int it = 0; it <= nkt; it++) {
        // ---- load tile `it` into registers ----
        if (it < nkt) {
            int kt = it * 32;
            // A rows (m)
            {
                const float* ar = Ap + (long)(m0 + arow) * lda + kt + akseg;
                if (vecA) {
#pragma unroll
                    for (int j4 = 0; j4 < 4; j4++) {
                        float4 v = make_float4(0.f, 0.f, 0.f, 0.f);
                        if (kt + akseg + j4 * 4 < K) v = *(const float4*)(ar + j4 * 4);
                        ra[j4*4+0] = v.x; ra[j4*4+1] = v.y; ra[j4*4+2] = v.z; ra[j4*4+3] = v.w;
                    }
                } else {
#pragma unroll
                    for (int j = 0; j < 16; j++)
                        ra[j] = (kt + akseg + j < K) ? ar[j] : 0.f;
                }
            }
            // B
            if (CONV) {
                int kg = kt + bk;
                int c  = kg / 9;
                int t9 = kg - c * 9;
                int dy = (t9 / 3 - 1) * dil;
                int dx = (t9 % 3 - 1) * dil;
                const float* base = Bp + (long)c * HW;
#pragma unroll
                for (int j = 0; j < 16; j++) {
                    int p = n0 + bn0 + j;
                    int h = (p >> 6) + dy;
                    int w = (p & 63) + dx;
                    float v = 0.f;
                    if ((unsigned)h < 64u && (unsigned)w < 64u) v = base[h * 64 + w];
                    rb[j] = v;
                }
            } else if (TRANSB) {
                const float* br = Bp + (long)(n0 + arow) * ldb + kt + akseg;
#pragma unroll
                for (int j4 = 0; j4 < 4; j4++) {
                    float4 v = make_float4(0.f, 0.f, 0.f, 0.f);
                    if (kt + akseg + j4 * 4 < K) v = *(const float4*)(br + j4 * 4);
                    rb[j4*4+0] = v.x; rb[j4*4+1] = v.y; rb[j4*4+2] = v.z; rb[j4*4+3] = v.w;
                }
            } else {
                const float* br = Bp + (long)(kt + bk) * ldb + n0 + bn0;
                bool ok = (kt + bk) < K;
#pragma unroll
                for (int j4 = 0; j4 < 4; j4++) {
                    float4 v = make_float4(0.f, 0.f, 0.f, 0.f);
                    if (ok) v = *(const float4*)(br + j4 * 4);
                    rb[j4*4+0] = v.x; rb[j4*4+1] = v.y; rb[j4*4+2] = v.z; rb[j4*4+3] = v.w;
                }
            }
        }

        // ---- compute on tile `it-1` ----
        if (it > 0) {
            uint32_t stA = sbase + (uint32_t)(((it - 1) & 1) * STAGE_BYTES);
            uint32_t stB = stA + 128 * ROWB;
            uint32_t abase = stA + (uint32_t)(wm + rowsel) * ROWB + colsel;
            uint32_t bbase = stB + (uint32_t)(wn + rowsel) * ROWB + colsel;
#pragma unroll
            for (int ks = 0; ks < 4; ks++) {
                uint32_t af[4][4];
#pragma unroll
                for (int mt = 0; mt < 4; mt++)
                    ldsm_x4(af[mt][0], af[mt][1], af[mt][2], af[mt][3],
                            abase + mt * 16 * ROWB + ks * 32);
                uint32_t bf[2][4];
#pragma unroll
                for (int ntp = 0; ntp < 2; ntp++)
                    ldsm_x4(bf[ntp][0], bf[ntp][1], bf[ntp][2], bf[ntp][3],
                            bbase + ntp * 16 * ROWB + ks * 32);
#pragma unroll
                for (int mt = 0; mt < 4; mt++) {
#pragma unroll
                    for (int nt = 0; nt < 4; nt++) {
                        int ntp = nt >> 1, par = nt & 1;
                        mma_tf32u(acc[mt][nt],
                                  af[mt][0], af[mt][1], af[mt][2], af[mt][3],
                                  bf[ntp][par ? 1 : 0], bf[ntp][par ? 3 : 2]);
                    }
                }
            }
        }

        // ---- store tile `it` (tf32-rounded) into stage it&1 ----
        if (it < nkt) {
            float* stA = sm + (it & 1) * (STAGE_BYTES / 4);
            float* stB = stA + 128 * LDK;
            // A / TRANSB-B share row-major layout on their row index
            float* arw = stA + arow * LDK + akseg;
#pragma unroll
            for (int j = 0; j < 16; j++) arw[j] = __uint_as_float(f2tf(ra[j]));
            if (TRANSB) {
                float* brw = stB + arow * LDK + akseg;
#pragma unroll
                for (int j = 0; j < 16; j++) brw[j] = __uint_as_float(f2tf(rb[j]));
            } else {
                // transpose store: [n][k]
#pragma unroll
                for (int j = 0; j < 16; j++)
                    stB[(bn0 + j) * LDK + bk] = __uint_as_float(f2tf(rb[j]));
            }
        }
        __syncthreads();
    }

    // ---- epilogue ----
    int r  = lane >> 2;
    int cg = lane & 3;
    float mu = 0.f, rs = 0.f;
    if (mode == EP_ADN) { mu = stats[2 * bb]; rs = stats[2 * bb + 1]; }
#pragma unroll
    for (int mt = 0; mt < 4; mt++) {
#pragma unroll
        for (int nt = 0; nt < 4; nt++) {
            int m1 = m0 + wm + mt * 16 + r;
            int m2 = m1 + 8;
            int nn = n0 + wn + nt * 8 + cg * 2;
            long i1 = (long)m1 * N + nn;
            long i2 = (long)m2 * N + nn;
            long base = (long)bb * sC_;
            Cp[i1]     = apply_ep(acc[mt][nt][0], mode, scale, m1, base + i1,     bias, t0, gamma, betaS, mid, gf, mu, rs);
            Cp[i1 + 1] = apply_ep(acc[mt][nt][1], mode, scale, m1, base + i1 + 1, bias, t0, gamma, betaS, mid, gf, mu, rs);
            Cp[i2]     = apply_ep(acc[mt][nt][2], mode, scale, m2, base + i2,     bias, t0, gamma, betaS, mid, gf, mu, rs);
            Cp[i2 + 1] = apply_ep(acc[mt][nt][3], mode, scale, m2, base + i2 + 1, bias, t0, gamma, betaS, mid, gf, mu, rs);
        }
    }
}

// ================= LayerNorm stats =================
__global__ void __launch_bounds__(256)
ln_part_kernel(const float* __restrict__ src) {
    int b = blockIdx.y, ch = blockIdx.x;
    const int CH = CHW / 64;
    const float* p = src + (long)b * CHW + (long)ch * CH;
    int tid = threadIdx.x;
    float s = 0.f, q = 0.f;
    for (int i = tid; i < CH; i += 256) { float v = p[i]; s += v; q += v * v; }
    __shared__ float shs[8], shq[8];
#pragma unroll
    for (int o = 16; o; o >>= 1) {
        s += __shfl_xor_sync(0xffffffffu, s, o);
        q += __shfl_xor_sync(0xffffffffu, q, o);
    }
    if ((tid & 31) == 0) { shs[tid >> 5] = s; shq[tid >> 5] = q; }
    __syncthreads();
    if (tid < 8) {
        s = shs[tid]; q = shq[tid];
#pragma unroll
        for (int o = 4; o; o >>= 1) {
            s += __shfl_xor_sync(0xffu, s, o);
            q += __shfl_xor_sync(0xffu, q, o);
        }
        if (tid == 0) {
            g_part[(b * 64 + ch) * 2 + 0] = s;
            g_part[(b * 64 + ch) * 2 + 1] = q;
        }
    }
}

__global__ void ln_final_kernel() {
    int b = blockIdx.x;
    int tid = threadIdx.x;
    float s = 0.f, q = 0.f;
    for (int i = tid; i < 64; i += 32) {
        s += g_part[(b * 64 + i) * 2 + 0];
        q += g_part[(b * 64 + i) * 2 + 1];
    }
#pragma unroll
    for (int o = 16; o; o >>= 1) {
        s += __shfl_xor_sync(0xffffffffu, s, o);
        q += __shfl_xor_sync(0xffffffffu, q, o);
    }
    if (tid == 0) {
        float mu = s / (float)CHW;
        float var = q / (float)CHW - mu * mu;
        g_stats[2 * b]     = mu;
        g_stats[2 * b + 1] = rsqrtf(var + 1e-5f);
    }
}

// ================= softmax =================
__global__ void __launch_bounds__(256)
softmax_kernel(float* __restrict__ S, int L) {
    long row = blockIdx.x;
    float* p = S + row * (long)L;
    int tid = threadIdx.x;
    __shared__ float sh[8];

    float mx = -3.4e38f;
    for (int i = tid; i < L; i += 256) mx = fmaxf(mx, p[i]);
#pragma unroll
    for (int o = 16; o; o >>= 1) mx = fmaxf(mx, __shfl_xor_sync(0xffffffffu, mx, o));
    if ((tid & 31) == 0) sh[tid >> 5] = mx;
    __syncthreads();
    if (tid < 8) {
        float v = sh[tid];
#pragma unroll
        for (int o = 4; o; o >>= 1) v = fmaxf(v, __shfl_xor_sync(0xffu, v, o));
        if (tid == 0) sh[0] = v;
    }
    __syncthreads();
    mx = sh[0];
    __syncthreads();

    float s = 0.f;
    for (int i = tid; i < L; i += 256) { float e = __expf(p[i] - mx); p[i] = e; s += e; }
#pragma unroll
    for (int o = 16; o; o >>= 1) s += __shfl_xor_sync(0xffffffffu, s, o);
    if ((tid & 31) == 0) sh[tid >> 5] = s;
    __syncthreads();
    if (tid < 8) {
        float v = sh[tid];
#pragma unroll
        for (int o = 4; o; o >>= 1) v += __shfl_xor_sync(0xffu, v, o);
        if (tid == 0) sh[0] = v;
    }
    __syncthreads();
    float inv = 1.f / sh[0];
    for (int i = tid; i < L; i += 256) p[i] *= inv;
}

// ================= patchify =================
__global__ void __launch_bounds__(256)
patchify_kernel(const float* __restrict__ src, float* __restrict__ dst, int c0, int P) {
    long i = (long)blockIdx.x * blockDim.x + threadIdx.x;
    const long per_b = 64L * HW;
    long total = (long)NB * per_b;
    if (i >= total) return;
    int ow = 64 / P;
    int D = 64 * P * P;
    int Nw = ow * ow;
    int d = (int)(i % D);
    long t = i / D;
    int n = (int)(t % Nw);
    int b = (int)(t / Nw);
    int c  = d / (P * P);
    int rr = d - c * (P * P);
    int py = rr / P, px = rr - (rr / P) * P;
    int iY = n / ow, jX = n - iY * ow;
    int h = iY * P + py, w = jX * P + px;
    dst[i] = src[((long)b * NC + c0 + c) * HW + h * 64 + w];
}

// ================= unpatch + residual =================
__global__ void __launch_bounds__(256)
unpatch_add_kernel(const float* __restrict__ x) {
    long i = (long)blockIdx.x * blockDim.x + threadIdx.x;
    long total = (long)NB * CHW;
    if (i >= total) return;
    int p = (int)(i & 4095);
    int c = (int)((i >> 12) & 127);
    int b = (int)(i >> 19);
    int h = p >> 6, w = p & 63;
    float y;
    if (c < 64) {
        int n = (h >> 1) * 32 + (w >> 1);
        int d = c * 4 + (h & 1) * 2 + (w & 1);
        y = g_y1[((long)b * 1024 + n) * 256 + d];
    } else {
        int n = (h >> 2) * 16 + (w >> 2);
        int d = (c - 64) * 16 + (h & 3) * 4 + (w & 3);
        y = g_y2[((long)b * 256 + n) * 1024 + d];
    }
    g_mid[i] = x[i] + y;
}

// ================= host side =================
static void tc_nn(const float* A, int lda, long sA,
                  const float* B, int ldb, long sB, float* C, long sC,
                  int M, int N, int K, int mode, float scale = 1.f,
                  const float* bias = nullptr, const float* t0 = nullptr,
                  const float* gamma = nullptr, const float* betaS = nullptr,
                  const float* stats = nullptr) {
    dim3 grid(N / 128, M / 128, NB);
    tc_gemm3<false, false><<<grid, 256, SMEM_BYTES>>>(A, lda, sA, B, ldb, sB, C, sC, N, K,
                                                      mode, scale, 1, bias, t0, gamma, betaS, stats,
                                                      nullptr, nullptr);
}

static void tc_nt(const float* A, int lda, long sA,
                  const float* B, int ldb, long sB, float* C, long sC,
                  int M, int N, int K, float scale) {
    dim3 grid(N / 128, M / 128, NB);
    tc_gemm3<true, false><<<grid, 256, SMEM_BYTES>>>(A, lda, sA, B, ldb, sB, C, sC, N, K,
                                                     EP_NONE, scale, 1, nullptr, nullptr, nullptr, nullptr, nullptr,
                                                     nullptr, nullptr);
}

static void tc_conv(const float* Wt, const float* X, float* C,
                    const float* bias, int dil, int mode,
                    const float* mid = nullptr, const float* gf = nullptr) {
    dim3 grid(32, 1, NB);
    tc_gemm3<false, true><<<grid, 256, SMEM_BYTES>>>(Wt, 1152, 0, X, 0, CHW, C, CHW, HW, 1152,
                                                     mode, 1.f, dil, bias, nullptr, nullptr, nullptr, nullptr,
                                                     mid, gf);
}

extern "C" void kernel_launch(void* const* d_in, const int* in_sizes, int n_in,
                              void* d_out, int out_size) {
    const float* x    = (const float*)d_in[0];
    const float* edge = (const float*)d_in[1];
    const float* seg  = (const float*)d_in[2];
    const float* pe   = (const float*)d_in[3];
    const float* ps   = (const float*)d_in[4];
    const float* q_w  = (const float*)d_in[5];
    const float* q_b  = (const float*)d_in[6];
    const float* k_w  = (const float*)d_in[7];
    const float* k_b  = (const float*)d_in[8];
    const float* v_w  = (const float*)d_in[9];
    const float* v_b  = (const float*)d_in[10];
    const float* d1_embed_w = (const float*)d_in[11];
    const float* d1_embed_b = (const float*)d_in[12];
    const float* d1_scale_w = (const float*)d_in[13];
    const float* d1_scale_b = (const float*)d_in[14];
    const float* d1_bias_w  = (const float*)d_in[15];
    const float* d1_bias_b  = (const float*)d_in[16];
    const float* d2_embed_w = (const float*)d_in[17];
    const float* d2_embed_b = (const float*)d_in[18];
    const float* d2_scale_w = (const float*)d_in[19];
    const float* d2_scale_b = (const float*)d_in[20];
    const float* d2_bias_w  = (const float*)d_in[21];
    const float* d2_bias_b  = (const float*)d_in[22];
    const float* sc_w  = (const float*)d_in[23];
    const float* sc_b  = (const float*)d_in[24];
    const float* bi1_w = (const float*)d_in[25];
    const float* bi1_b = (const float*)d_in[26];
    const float* bi2_w = (const float*)d_in[27];
    const float* bi2_b = (const float*)d_in[28];
    float* out = (float*)d_out;

    // allow 72KB dynamic smem (idempotent)
    cudaFuncSetAttribute(tc_gemm3<false, false>, cudaFuncAttributeMaxDynamicSharedMemorySize, SMEM_BYTES);
    cudaFuncSetAttribute(tc_gemm3<true,  false>, cudaFuncAttributeMaxDynamicSharedMemorySize, SMEM_BYTES);
    cudaFuncSetAttribute(tc_gemm3<false, true >, cudaFuncAttributeMaxDynamicSharedMemorySize, SMEM_BYTES);

    float *aux_, *a_, *gamma_, *betaS_, *t0_, *q_, *k_, *v_, *mid_, *o_, *gf_, *tmp_;
    float *qp1_, *kp1_, *vp1_, *qp2_, *kp2_, *vp2_, *s1_, *s2_, *y1_, *y2_, *stats_;
    cudaGetSymbolAddress((void**)&aux_,   g_aux);
    cudaGetSymbolAddress((void**)&a_,     g_a);
    cudaGetSymbolAddress((void**)&gamma_, g_gamma);
    cudaGetSymbolAddress((void**)&betaS_, g_betaS);
    cudaGetSymbolAddress((void**)&t0_,    g_t0);
    cudaGetSymbolAddress((void**)&q_,     g_q);
    cudaGetSymbolAddress((void**)&k_,     g_k);
    cudaGetSymbolAddress((void**)&v_,     g_v);
    cudaGetSymbolAddress((void**)&mid_,   g_mid);
    cudaGetSymbolAddress((void**)&o_,     g_o);
    cudaGetSymbolAddress((void**)&gf_,    g_gf);
    cudaGetSymbolAddress((void**)&tmp_,   g_tmp);
    cudaGetSymbolAddress((void**)&qp1_,   g_qp1);
    cudaGetSymbolAddress((void**)&kp1_,   g_kp1);
    cudaGetSymbolAddress((void**)&vp1_,   g_vp1);
    cudaGetSymbolAddress((void**)&qp2_,   g_qp2);
    cudaGetSymbolAddress((void**)&kp2_,   g_kp2);
    cudaGetSymbolAddress((void**)&vp2_,   g_vp2);
    cudaGetSymbolAddress((void**)&s1_,    g_s1);
    cudaGetSymbolAddress((void**)&s2_,    g_s2);
    cudaGetSymbolAddress((void**)&y1_,    g_y1);
    cudaGetSymbolAddress((void**)&y2_,    g_y2);
    cudaGetSymbolAddress((void**)&stats_, g_stats);

    // 1. aux concat
    {
        long total = (long)NB * AUXC * HW;
        concat_aux_kernel<<<(int)((total + 255) / 256), 256>>>(edge, seg, pe, ps);
    }

    // 2. ADN-1 shared pieces
    tc_nn(d1_embed_w, AUXC, 0, aux_, HW, (long)AUXC * HW, a_, CHW,
          NC, HW, AUXC, EP_BIAS, 1.f, d1_embed_b);
    tc_nn(d1_scale_w, NC, 0, a_, HW, CHW, gamma_, CHW,
          NC, HW, NC, EP_BIAS, 1.f, d1_scale_b);
    tc_nn(d1_bias_w + NC, 2 * NC, 0, a_, HW, CHW, betaS_, CHW,
          NC, HW, NC, EP_BIAS, 1.f, d1_bias_b);

    // 3. q / k / v
    const float* tw[3] = { q_w, k_w, v_w };
    const float* tb[3] = { q_b, k_b, v_b };
    float* tout[3] = { q_, k_, v_ };
    for (int t = 0; t < 3; t++) {
        tc_nn(tw[t], NC, 0, x, HW, CHW, t0_, CHW, NC, HW, NC, EP_BIAS, 1.f, tb[t]);
        ln_part_kernel<<<dim3(64, NB), 256>>>(t0_);
        ln_final_kernel<<<NB, 32>>>();
        tc_nn(d1_bias_w, 2 * NC, 0, t0_, HW, CHW, tout[t], CHW,
              NC, HW, NC, EP_ADN, 1.f, nullptr, t0_, gamma_, betaS_, stats_);
    }

    // 4. patchify
    {
        int blocks = (int)(((long)NB * 64 * HW + 255) / 256);
        patchify_kernel<<<blocks, 256>>>(q_, qp1_, 0, 2);
        patchify_kernel<<<blocks, 256>>>(k_, kp1_, 0, 2);
        patchify_kernel<<<blocks, 256>>>(v_, vp1_, 0, 2);
        patchify_kernel<<<blocks, 256>>>(q_, qp2_, 64, 4);
        patchify_kernel<<<blocks, 256>>>(k_, kp2_, 64, 4);
        patchify_kernel<<<blocks, 256>>>(v_, vp2_, 64, 4);
    }

    // 5. attention scale 1: 1024 tokens, d=256
    tc_nt(qp1_, 256, 1024L * 256, kp1_, 256, 1024L * 256, s1_, 1024L * 1024,
          1024, 1024, 256, 0.0625f);
    softmax_kernel<<<NB * 1024, 256>>>(s1_, 1024);
    tc_nn(s1_, 1024, 1024L * 1024, vp1_, 256, 1024L * 256, y1_, 1024L * 256,
          1024, 256, 1024, EP_NONE);

    // 6. attention scale 2: 256 tokens, d=1024
    tc_nt(qp2_, 1024, 256L * 1024, kp2_, 1024, 256L * 1024, s2_, 256L * 256,
          256, 256, 1024, 0.03125f);
    softmax_kernel<<<NB * 256, 256>>>(s2_, 256);
    tc_nn(s2_, 256, 256L * 256, vp2_, 1024, 256L * 1024, y2_, 256L * 1024,
          256, 1024, 256, EP_NONE);

    // 7. mid = x + unpatch(y1,y2)
    unpatch_add_kernel<<<(int)(((long)NB * CHW + 255) / 256), 256>>>(x);

    // 8. ADN-2
    tc_nn(d2_embed_w, AUXC, 0, aux_, HW, (long)AUXC * HW, a_, CHW,
          NC, HW, AUXC, EP_BIAS, 1.f, d2_embed_b);
    tc_nn(d2_scale_w, NC, 0, a_, HW, CHW, gamma_, CHW,
          NC, HW, NC, EP_BIAS, 1.f, d2_scale_b);
    tc_nn(d2_bias_w + NC, 2 * NC, 0, a_, HW, CHW, betaS_, CHW,
          NC, HW, NC, EP_BIAS, 1.f, d2_bias_b);
    ln_part_kernel<<<dim3(64, NB), 256>>>(mid_);
    ln_final_kernel<<<NB, 32>>>();
    tc_nn(d2_bias_w, 2 * NC, 0, mid_, HW, CHW, o_, CHW,
          NC, HW, NC, EP_ADN, 1.f, nullptr, mid_, gamma_, betaS_, stats_);

    // 9. conv3x3 chain
    tc_conv(sc_w,  o_,   gf_, sc_b,  1, EP_TANH);
    tc_conv(bi1_w, o_,   tmp_, bi1_b, 2, EP_GELU);
    tc_conv(bi2_w, tmp_, out, bi2_b, 1, EP_FINAL, mid_, gf_);
}

// round 4
// speedup vs baseline: 2.7383x; 1.2648x over previous
#include <cuda_runtime.h>
#include <cuda_fp16.h>
#include <math.h>
#include <stdint.h>

// ---------------- problem constants ----------------
#define NB 16
#define NC 128
#define HW 4096           // 64*64
#define CHW (NC*HW)       // 524288
#define AUXC 277

// ---------------- scratch ----------------
__device__ float g_aux  [NB*AUXC*HW];
__device__ float g_a    [NB*CHW];
__device__ float g_gamma[NB*CHW];
__device__ float g_betaS[NB*CHW];
__device__ float g_t0   [NB*CHW];
__device__ float g_mid  [NB*CHW];
__device__ float g_o    [NB*CHW];
__device__ float g_gf   [NB*CHW];
__device__ float g_tmp  [NB*CHW];
__device__ float g_qp1  [NB*1024*256];
__device__ float g_kp1  [NB*1024*256];
__device__ float g_vp1  [NB*1024*256];
__device__ float g_qp2  [NB*256*1024];
__device__ float g_kp2  [NB*256*1024];
__device__ float g_vp2  [NB*256*1024];
__device__ float g_s1   [NB*1024L*1024];
__device__ float g_s2   [NB*256*256];
__device__ float g_stats[NB*2];
__device__ float g_part [NB*64*2];

// ---------------- epilogue modes ----------------
#define EP_BIAS  0
#define EP_ADN   1
#define EP_NONE  2
#define EP_TANH  3
#define EP_GELU  4
#define EP_FINAL 5
#define EP_QKV   6   // ADN + direct patched write to dst1 (c<64, P=2) / dst2 (c>=64, P=4)
#define EP_PV1   7   // y1 -> mid (channels 0..63), + x residual
#define EP_PV2   8   // y2 -> mid (channels 64..127), + x residual

// ---------------- smem geometry (fp16) ----------------
#define LDH 40                    // halfs per row (32 + 8 pad)
#define ROWB (LDH*2)              // 80 bytes per row
#define STAGE_BYTES (256*ROWB)    // A(128 rows) + B(128 rows) = 20480
#define SMEM_BYTES (2*STAGE_BYTES)  // 40960

// ---------------- helpers ----------------
__device__ __forceinline__ void ldsm_x4(uint32_t& r0, uint32_t& r1, uint32_t& r2, uint32_t& r3,
                                        uint32_t addr) {
    asm volatile("ldmatrix.sync.aligned.m8n8.x4.shared.b16 {%0,%1,%2,%3}, [%4];"
                 : "=r"(r0), "=r"(r1), "=r"(r2), "=r"(r3) : "r"(addr));
}

__device__ __forceinline__ void mma_f16(float* c,
                                        uint32_t a0, uint32_t a1, uint32_t a2, uint32_t a3,
                                        uint32_t b0, uint32_t b1) {
    asm volatile(
        "mma.sync.aligned.m16n8k16.row.col.f32.f16.f16.f32 "
        "{%0,%1,%2,%3}, {%4,%5,%6,%7}, {%8,%9}, {%0,%1,%2,%3};"
        : "+f"(c[0]), "+f"(c[1]), "+f"(c[2]), "+f"(c[3])
        : "r"(a0), "r"(a1), "r"(a2), "r"(a3), "r"(b0), "r"(b1));
}

__device__ __forceinline__ uint32_t pack_h2(float lo, float hi) {
    half2 h = __floats2half2_rn(lo, hi);
    return *(uint32_t*)&h;
}

// ================= concat aux =================
__global__ void __launch_bounds__(256)
concat_aux_kernel(const float* __restrict__ edge, const float* __restrict__ seg,
                  const float* __restrict__ pe,   const float* __restrict__ ps) {
    long i = (long)blockIdx.x * blockDim.x + threadIdx.x;
    long total = (long)NB * AUXC * HW;
    if (i >= total) return;
    int p = (int)(i % HW);
    long t = i / HW;
    int c = (int)(t % AUXC);
    int b = (int)(t / AUXC);
    float v;
    if (c < 128)       v = edge[((long)b*128 + c)      * HW + p];
    else if (c < 256)  v = seg [((long)b*128 + (c-128))* HW + p];
    else if (c == 256) v = pe  [(long)b * HW + p];
    else               v = ps  [((long)b*20 + (c-257)) * HW + p];
    g_aux[i] = v;
}

// ================= tensor-core GEMM (fp16 operands, fp32 accum) =================
// TRANSB=0, CONV=0 : C[m,n] = A[m,k] * B[k,n]   (B row-major [K][N])
// TRANSB=1         : C[m,n] = A[m,k] * B[n,k]   (B row-major [N][K])
// CONV=1           : implicit conv3x3 GEMM, B gathered from X [128][64][64], K=1152
template<bool TRANSB, bool CONV>
__global__ void __launch_bounds__(256)
tc_gemm4(const float* __restrict__ A, int lda, long sA_,
         const float* __restrict__ Bm, int ldb, long sB_,
         float* __restrict__ Cm, long sC_,
         int N, int K, int mode, float scale, int dil,
         const float* __restrict__ bias,
         const float* __restrict__ t0,
         const float* __restrict__ gamma,
         const float* __restrict__ betaS,
         const float* __restrict__ stats,
         const float* __restrict__ mid,
         const float* __restrict__ gf,
         float* __restrict__ dst1,
         float* __restrict__ dst2)
{
    extern __shared__ half sm16[];
    int bb = blockIdx.z;
    int n0 = blockIdx.x * 128;
    int m0 = blockIdx.y * 128;
    const float* Ap = A  + (long)bb * sA_;
    const float* Bp = Bm + (long)bb * sB_;
    float* Cp       = Cm + (long)bb * sC_;

    int tid  = threadIdx.x;
    int lane = tid & 31;
    int warp = tid >> 5;
    int wm = (warp >> 2) * 64;
    int wn = (warp & 3) * 32;

    // loader geometry
    int arow  = tid >> 1;            // 0..127
    int akseg = (tid & 1) * 16;      // 0 / 16
    int bk    = tid & 31;            // k within tile (nn / conv B)
    int bn0   = (tid >> 5) * 16;     // n segment

    // ldmatrix addressing: row = lane&15, 16B column select = (lane>>4)
    uint32_t sbase = (uint32_t)__cvta_generic_to_shared(sm16);
    int rowsel = lane & 15;
    int colsel = (lane >> 4) * 16;

    bool vecA = ((lda & 3) == 0) && ((K & 3) == 0);

    float ra[16], rb[16];
    float acc[4][4][4] = {};

    int nkt = (K + 31) >> 5;

    for (int it = 0; it <= nkt; it++) {
        // ---- global load tile `it` ----
        if (it < nkt) {
            int kt = it * 32;
            {
                const float* ar = Ap + (long)(m0 + arow) * lda + kt + akseg;
                if (vecA) {
#pragma unroll
                    for (int j4 = 0; j4 < 4; j4++) {
                        float4 v = make_float4(0.f, 0.f, 0.f, 0.f);
                        if (kt + akseg + j4 * 4 < K) v = *(const float4*)(ar + j4 * 4);
                        ra[j4*4+0] = v.x; ra[j4*4+1] = v.y; ra[j4*4+2] = v.z; ra[j4*4+3] = v.w;
                    }
                } else {
#pragma unroll
                    for (int j = 0; j < 16; j++)
                        ra[j] = (kt + akseg + j < K) ? ar[j] : 0.f;
                }
            }
            if (CONV) {
                int kg = kt + bk;
                int c  = kg / 9;
                int t9 = kg - c * 9;
                int dy = (t9 / 3 - 1) * dil;
                int dx = (t9 % 3 - 1) * dil;
                const float* base = Bp + (long)c * HW;
#pragma unroll
                for (int j = 0; j < 16; j++) {
                    int p = n0 + bn0 + j;
                    int h = (p >> 6) + dy;
                    int w = (p & 63) + dx;
                    float v = 0.f;
                    if ((unsigned)h < 64u && (unsigned)w < 64u) v = base[h * 64 + w];
                    rb[j] = v;
                }
            } else if (TRANSB) {
                const float* br = Bp + (long)(n0 + arow) * ldb + kt + akseg;
#pragma unroll
                for (int j4 = 0; j4 < 4; j4++) {
                    float4 v = make_float4(0.f, 0.f, 0.f, 0.f);
                    if (kt + akseg + j4 * 4 < K) v = *(const float4*)(br + j4 * 4);
                    rb[j4*4+0] = v.x; rb[j4*4+1] = v.y; rb[j4*4+2] = v.z; rb[j4*4+3] = v.w;
                }
            } else {
                const float* br = Bp + (long)(kt + bk) * ldb + n0 + bn0;
                bool ok = (kt + bk) < K;
#pragma unroll
                for (int j4 = 0; j4 < 4; j4++) {
                    float4 v = make_float4(0.f, 0.f, 0.f, 0.f);
                    if (ok) v = *(const float4*)(br + j4 * 4);
                    rb[j4*4+0] = v.x; rb[j4*4+1] = v.y; rb[j4*4+2] = v.z; rb[j4*4+3] = v.w;
                }
            }
        }

        // ---- compute tile `it-1` ----
        if (it > 0) {
            uint32_t stA = sbase + (uint32_t)(((it - 1) & 1) * STAGE_BYTES);
            uint32_t stB = stA + 128 * ROWB;
            uint32_t abase = stA + (uint32_t)(wm + rowsel) * ROWB + colsel;
            uint32_t bbase = stB + (uint32_t)(wn + rowsel) * ROWB + colsel;
#pragma unroll
            for (int ks = 0; ks < 2; ks++) {
                uint32_t af[4][4];
#pragma unroll
                for (int mt = 0; mt < 4; mt++)
                    ldsm_x4(af[mt][0], af[mt][1], af[mt][2], af[mt][3],
                            abase + mt * 16 * ROWB + ks * 32);
                uint32_t bf[2][4];
#pragma unroll
                for (int ntp = 0; ntp < 2; ntp++)
                    ldsm_x4(bf[ntp][0], bf[ntp][1], bf[ntp][2], bf[ntp][3],
                            bbase + ntp * 16 * ROWB + ks * 32);
#pragma unroll
                for (int mt = 0; mt < 4; mt++) {
#pragma unroll
                    for (int nt = 0; nt < 4; nt++) {
                        int ntp = nt >> 1, par = nt & 1;
                        mma_f16(acc[mt][nt],
                                af[mt][0], af[mt][1], af[mt][2], af[mt][3],
                                bf[ntp][par ? 1 : 0], bf[ntp][par ? 3 : 2]);
                    }
                }
            }
        }

        // ---- store tile `it` into stage it&1 (fp16) ----
        if (it < nkt) {
            half* stA = sm16 + (it & 1) * (STAGE_BYTES / 2);
            half* stB = stA + 128 * LDH;
            uint32_t* arw = (uint32_t*)(stA + arow * LDH + akseg);
#pragma unroll
            for (int j2 = 0; j2 < 8; j2++) arw[j2] = pack_h2(ra[j2*2], ra[j2*2+1]);
            if (TRANSB) {
                uint32_t* brw = (uint32_t*)(stB + arow * LDH + akseg);
#pragma unroll
                for (int j2 = 0; j2 < 8; j2++) brw[j2] = pack_h2(rb[j2*2], rb[j2*2+1]);
            } else {
#pragma unroll
                for (int j = 0; j < 16; j++)
                    stB[(bn0 + j) * LDH + bk] = __float2half_rn(rb[j]);
            }
        }
        __syncthreads();
    }

    // ---- epilogue ----
    int r  = lane >> 2;
    int cg = lane & 3;
    float mu = 0.f, rs = 0.f;
    if (mode == EP_ADN || mode == EP_QKV) { mu = stats[2 * bb]; rs = stats[2 * bb + 1]; }
    long bbC = (long)bb * sC_;

    auto emit = [&](float v, int m, int n) {
        if (mode == EP_BIAS) {
            Cp[(long)m * N + n] = v + bias[m];
        } else if (mode == EP_ADN) {
            long gidx = bbC + (long)m * N + n;
            Cp[(long)m * N + n] = (t0[gidx] - mu) * rs * gamma[gidx] + v + betaS[gidx];
        } else if (mode == EP_NONE) {
            Cp[(long)m * N + n] = v * scale;
        } else if (mode == EP_TANH) {
            Cp[(long)m * N + n] = tanhf(v + bias[m]);
        } else if (mode == EP_GELU) {
            float u = v + bias[m];
            Cp[(long)m * N + n] = 0.5f * u * (1.f + erff(u * 0.70710678118654752f));
        } else if (mode == EP_FINAL) {
            long gidx = bbC + (long)m * N + n;
            Cp[(long)m * N + n] = mid[gidx] * gf[gidx] + v + bias[m];
        } else if (mode == EP_QKV) {
            long gidx = bbC + (long)m * N + n;
            float val = (t0[gidx] - mu) * rs * gamma[gidx] + v + betaS[gidx];
            int h = n >> 6, w = n & 63;
            if (m < 64) {
                int nn = (h >> 1) * 32 + (w >> 1);
                int d  = m * 4 + (h & 1) * 2 + (w & 1);
                dst1[(long)bb * (1024L*256) + (long)nn * 256 + d] = val;
            } else {
                int nn = (h >> 2) * 16 + (w >> 2);
                int d  = (m - 64) * 16 + (h & 3) * 4 + (w & 3);
                dst2[(long)bb * (256L*1024) + (long)nn * 1024 + d] = val;
            }
        } else if (mode == EP_PV1) {
            // m = token (0..1023), n = d (0..255) -> mid[c<64][h][w] = x + v
            int c  = n >> 2;
            int py = (n >> 1) & 1, px = n & 1;
            int h = (m >> 5) * 2 + py, w = (m & 31) * 2 + px;
            long idx = (long)c * HW + h * 64 + w;
            Cp[idx] = t0[bbC + idx] + v;
        } else { // EP_PV2: m = token (0..255), n = d (0..1023)
            int c  = 64 + (n >> 4);
            int py = (n >> 2) & 3, px = n & 3;
            int h = (m >> 4) * 4 + py, w = (m & 15) * 4 + px;
            long idx = (long)c * HW + h * 64 + w;
            Cp[idx] = t0[bbC + idx] + v;
        }
    };

#pragma unroll
    for (int mt = 0; mt < 4; mt++) {
#pragma unroll
        for (int nt = 0; nt < 4; nt++) {
            int m1 = m0 + wm + mt * 16 + r;
            int m2 = m1 + 8;
            int nn = n0 + wn + nt * 8 + cg * 2;
            emit(acc[mt][nt][0], m1, nn);
            emit(acc[mt][nt][1], m1, nn + 1);
            emit(acc[mt][nt][2], m2, nn);
            emit(acc[mt][nt][3], m2, nn + 1);
        }
    }
}

// ================= LayerNorm stats =================
__global__ void __launch_bounds__(256)
ln_part_kernel(const float* __restrict__ src) {
    int b = blockIdx.y, ch = blockIdx.x;
    const int CH = CHW / 64;
    const float* p = src + (long)b * CHW + (long)ch * CH;
    int tid = threadIdx.x;
    float s = 0.f, q = 0.f;
    for (int i = tid; i < CH; i += 256) { float v = p[i]; s += v; q += v * v; }
    __shared__ float shs[8], shq[8];
#pragma unroll
    for (int o = 16; o; o >>= 1) {
        s += __shfl_xor_sync(0xffffffffu, s, o);
        q += __shfl_xor_sync(0xffffffffu, q, o);
    }
    if ((tid & 31) == 0) { shs[tid >> 5] = s; shq[tid >> 5] = q; }
    __syncthreads();
    if (tid < 8) {
        s = shs[tid]; q = shq[tid];
#pragma unroll
        for (int o = 4; o; o >>= 1) {
            s += __shfl_xor_sync(0xffu, s, o);
            q += __shfl_xor_sync(0xffu, q, o);
        }
        if (tid == 0) {
            g_part[(b * 64 + ch) * 2 + 0] = s;
            g_part[(b * 64 + ch) * 2 + 1] = q;
        }
    }
}

__global__ void ln_final_kernel() {
    int b = blockIdx.x;
    int tid = threadIdx.x;
    float s = 0.f, q = 0.f;
    for (int i = tid; i < 64; i += 32) {
        s += g_part[(b * 64 + i) * 2 + 0];
        q += g_part[(b * 64 + i) * 2 + 1];
    }
#pragma unroll
    for (int o = 16; o; o >>= 1) {
        s += __shfl_xor_sync(0xffffffffu, s, o);
        q += __shfl_xor_sync(0xffffffffu, q, o);
    }
    if (tid == 0) {
        float mu = s / (float)CHW;
        float var = q / (float)CHW - mu * mu;
        g_stats[2 * b]     = mu;
        g_stats[2 * b + 1] = rsqrtf(var + 1e-5f);
    }
}

// ================= softmax =================
__global__ void __launch_bounds__(256)
softmax_kernel(float* __restrict__ S, int L) {
    long row = blockIdx.x;
    float* p = S + row * (long)L;
    int tid = threadIdx.x;
    __shared__ float sh[8];

    float mx = -3.4e38f;
    for (int i = tid; i < L; i += 256) mx = fmaxf(mx, p[i]);
#pragma unroll
    for (int o = 16; o; o >>= 1) mx = fmaxf(mx, __shfl_xor_sync(0xffffffffu, mx, o));
    if ((tid & 31) == 0) sh[tid >> 5] = mx;
    __syncthreads();
    if (tid < 8) {
        float v = sh[tid];
#pragma unroll
        for (int o = 4; o; o >>= 1) v = fmaxf(v, __shfl_xor_sync(0xffu, v, o));
        if (tid == 0) sh[0] = v;
    }
    __syncthreads();
    mx = sh[0];
    __syncthreads();

    float s = 0.f;
    for (int i = tid; i < L; i += 256) { float e = __expf(p[i] - mx); p[i] = e; s += e; }
#pragma unroll
    for (int o = 16; o; o >>= 1) s += __shfl_xor_sync(0xffffffffu, s, o);
    if ((tid & 31) == 0) sh[tid >> 5] = s;
    __syncthreads();
    if (tid < 8) {
        float v = sh[tid];
#pragma unroll
        for (int o = 4; o; o >>= 1) v += __shfl_xor_sync(0xffu, v, o);
        if (tid == 0) sh[0] = v;
    }
    __syncthreads();
    float inv = 1.f / sh[0];
    for (int i = tid; i < L; i += 256) p[i] *= inv;
}

// ================= host side =================
static void tc_gen(const float* A, int lda, long sA,
                   const float* B, int ldb, long sB, float* C, long sC,
                   int M, int N, int K, int mode, float scale,
                   const float* bias, const float* t0,
                   const float* gamma, const float* betaS, const float* stats,
                   const float* mid, const float* gf,
                   float* dst1, float* dst2) {
    dim3 grid(N / 128, M / 128, NB);
    tc_gemm4<false, false><<<grid, 256, SMEM_BYTES>>>(A, lda, sA, B, ldb, sB, C, sC, N, K,
                                                      mode, scale, 1, bias, t0, gamma, betaS, stats,
                                                      mid, gf, dst1, dst2);
}

static void tc_nn(const float* A, int lda, long sA,
                  const float* B, int ldb, long sB, float* C, long sC,
                  int M, int N, int K, int mode, float scale = 1.f,
                  const float* bias = nullptr, const float* t0 = nullptr,
                  const float* gamma = nullptr, const float* betaS = nullptr,
                  const float* stats = nullptr) {
    tc_gen(A, lda, sA, B, ldb, sB, C, sC, M, N, K, mode, scale,
           bias, t0, gamma, betaS, stats, nullptr, nullptr, nullptr, nullptr);
}

static void tc_nt(const float* A, int lda, long sA,
                  const float* B, int ldb, long sB, float* C, long sC,
                  int M, int N, int K, float scale) {
    dim3 grid(N / 128, M / 128, NB);
    tc_gemm4<true, false><<<grid, 256, SMEM_BYTES>>>(A, lda, sA, B, ldb, sB, C, sC, N, K,
                                                     EP_NONE, scale, 1, nullptr, nullptr, nullptr, nullptr, nullptr,
                                                     nullptr, nullptr, nullptr, nullptr);
}

static void tc_conv(const float* Wt, const float* X, float* C,
                    const float* bias, int dil, int mode,
                    const float* mid = nullptr, const float* gf = nullptr) {
    dim3 grid(32, 1, NB);
    tc_gemm4<false, true><<<grid, 256, SMEM_BYTES>>>(Wt, 1152, 0, X, 0, CHW, C, CHW, HW, 1152,
                                                     mode, 1.f, dil, bias, nullptr, nullptr, nullptr, nullptr,
                                                     mid, gf, nullptr, nullptr);
}

extern "C" void kernel_launch(void* const* d_in, const int* in_sizes, int n_in,
                              void* d_out, int out_size) {
    const float* x    = (const float*)d_in[0];
    const float* edge = (const float*)d_in[1];
    const float* seg  = (const float*)d_in[2];
    const float* pe   = (const float*)d_in[3];
    const float* ps   = (const float*)d_in[4];
    const float* q_w  = (const float*)d_in[5];
    const float* q_b  = (const float*)d_in[6];
    const float* k_w  = (const float*)d_in[7];
    const float* k_b  = (const float*)d_in[8];
    const float* v_w  = (const float*)d_in[9];
    const float* v_b  = (const float*)d_in[10];
    const float* d1_embed_w = (const float*)d_in[11];
    const float* d1_embed_b = (const float*)d_in[12];
    const float* d1_scale_w = (const float*)d_in[13];
    const float* d1_scale_b = (const float*)d_in[14];
    const float* d1_bias_w  = (const float*)d_in[15];
    const float* d1_bias_b  = (const float*)d_in[16];
    const float* d2_embed_w = (const float*)d_in[17];
    const float* d2_embed_b = (const float*)d_in[18];
    const float* d2_scale_w = (const float*)d_in[19];
    const float* d2_scale_b = (const float*)d_in[20];
    const float* d2_bias_w  = (const float*)d_in[21];
    const float* d2_bias_b  = (const float*)d_in[22];
    const float* sc_w  = (const float*)d_in[23];
    const float* sc_b  = (const float*)d_in[24];
    const float* bi1_w = (const float*)d_in[25];
    const float* bi1_b = (const float*)d_in[26];
    const float* bi2_w = (const float*)d_in[27];
    const float* bi2_b = (const float*)d_in[28];
    float* out = (float*)d_out;

    cudaFuncSetAttribute(tc_gemm4<false, false>, cudaFuncAttributeMaxDynamicSharedMemorySize, SMEM_BYTES);
    cudaFuncSetAttribute(tc_gemm4<true,  false>, cudaFuncAttributeMaxDynamicSharedMemorySize, SMEM_BYTES);
    cudaFuncSetAttribute(tc_gemm4<false, true >, cudaFuncAttributeMaxDynamicSharedMemorySize, SMEM_BYTES);

    float *aux_, *a_, *gamma_, *betaS_, *t0_, *mid_, *o_, *gf_, *tmp_;
    float *qp1_, *kp1_, *vp1_, *qp2_, *kp2_, *vp2_, *s1_, *s2_, *stats_;
    cudaGetSymbolAddress((void**)&aux_,   g_aux);
    cudaGetSymbolAddress((void**)&a_,     g_a);
    cudaGetSymbolAddress((void**)&gamma_, g_gamma);
    cudaGetSymbolAddress((void**)&betaS_, g_betaS);
    cudaGetSymbolAddress((void**)&t0_,    g_t0);
    cudaGetSymbolAddress((void**)&mid_,   g_mid);
    cudaGetSymbolAddress((void**)&o_,     g_o);
    cudaGetSymbolAddress((void**)&gf_,    g_gf);
    cudaGetSymbolAddress((void**)&tmp_,   g_tmp);
    cudaGetSymbolAddress((void**)&qp1_,   g_qp1);
    cudaGetSymbolAddress((void**)&kp1_,   g_kp1);
    cudaGetSymbolAddress((void**)&vp1_,   g_vp1);
    cudaGetSymbolAddress((void**)&qp2_,   g_qp2);
    cudaGetSymbolAddress((void**)&kp2_,   g_kp2);
    cudaGetSymbolAddress((void**)&vp2_,   g_vp2);
    cudaGetSymbolAddress((void**)&s1_,    g_s1);
    cudaGetSymbolAddress((void**)&s2_,    g_s2);
    cudaGetSymbolAddress((void**)&stats_, g_stats);

    // 1. aux concat
    {
        long total = (long)NB * AUXC * HW;
        concat_aux_kernel<<<(int)((total + 255) / 256), 256>>>(edge, seg, pe, ps);
    }

    // 2. ADN-1 shared pieces
    tc_nn(d1_embed_w, AUXC, 0, aux_, HW, (long)AUXC * HW, a_, CHW,
          NC, HW, AUXC, EP_BIAS, 1.f, d1_embed_b);
    tc_nn(d1_scale_w, NC, 0, a_, HW, CHW, gamma_, CHW,
          NC, HW, NC, EP_BIAS, 1.f, d1_scale_b);
    tc_nn(d1_bias_w + NC, 2 * NC, 0, a_, HW, CHW, betaS_, CHW,
          NC, HW, NC, EP_BIAS, 1.f, d1_bias_b);

    // 3. q / k / v : conv1x1 -> LN stats -> fused ADN with patched write
    const float* tw[3] = { q_w, k_w, v_w };
    const float* tb[3] = { q_b, k_b, v_b };
    float* p1[3] = { qp1_, kp1_, vp1_ };
    float* p2[3] = { qp2_, kp2_, vp2_ };
    for (int t = 0; t < 3; t++) {
        tc_nn(tw[t], NC, 0, x, HW, CHW, t0_, CHW, NC, HW, NC, EP_BIAS, 1.f, tb[t]);
        ln_part_kernel<<<dim3(64, NB), 256>>>(t0_);
        ln_final_kernel<<<NB, 32>>>();
        tc_gen(d1_bias_w, 2 * NC, 0, t0_, HW, CHW, t0_, CHW,
               NC, HW, NC, EP_QKV, 1.f, nullptr, t0_, gamma_, betaS_, stats_,
               nullptr, nullptr, p1[t], p2[t]);
    }

    // 4. attention scale 1: 1024 tokens, d=256 (PV writes mid directly)
    tc_nt(qp1_, 256, 1024L * 256, kp1_, 256, 1024L * 256, s1_, 1024L * 1024,
          1024, 1024, 256, 0.0625f);
    softmax_kernel<<<NB * 1024, 256>>>(s1_, 1024);
    tc_gen(s1_, 1024, 1024L * 1024, vp1_, 256, 1024L * 256, mid_, CHW,
           1024, 256, 1024, EP_PV1, 1.f, nullptr, x, nullptr, nullptr, nullptr,
           nullptr, nullptr, nullptr, nullptr);

    // 5. attention scale 2: 256 tokens, d=1024
    tc_nt(qp2_, 1024, 256L * 1024, kp2_, 1024, 256L * 1024, s2_, 256L * 256,
          256, 256, 1024, 0.03125f);
    softmax_kernel<<<NB * 256, 256>>>(s2_, 256);
    tc_gen(s2_, 256, 256L * 256, vp2_, 1024, 256L * 1024, mid_, CHW,
           256, 1024, 256, EP_PV2, 1.f, nullptr, x, nullptr, nullptr, nullptr,
           nullptr, nullptr, nullptr, nullptr);

    // 6. ADN-2
    tc_nn(d2_embed_w, AUXC, 0, aux_, HW, (long)AUXC * HW, a_, CHW,
          NC, HW, AUXC, EP_BIAS, 1.f, d2_embed_b);
    tc_nn(d2_scale_w, NC, 0, a_, HW, CHW, gamma_, CHW,
          NC, HW, NC, EP_BIAS, 1.f, d2_scale_b);
    tc_nn(d2_bias_w + NC, 2 * NC, 0, a_, HW, CHW, betaS_, CHW,
          NC, HW, NC, EP_BIAS, 1.f, d2_bias_b);
    ln_part_kernel<<<dim3(64, NB), 256>>>(mid_);
    ln_final_kernel<<<NB, 32>>>();
    tc_nn(d2_bias_w, 2 * NC, 0, mid_, HW, CHW, o_, CHW,
          NC, HW, NC, EP_ADN, 1.f, nullptr, mid_, gamma_, betaS_, stats_);

    // 7. conv3x3 chain
    tc_conv(sc_w,  o_,   gf_,  sc_b,  1, EP_TANH);
    tc_conv(bi1_w, o_,   tmp_, bi1_b, 2, EP_GELU);
    tc_conv(bi2_w, tmp_, out,  bi2_b, 1, EP_FINAL, mid_, gf_);
}